// round 11
// baseline (speedup 1.0000x reference)
#include <cuda_runtime.h>
#include <cuda_bf16.h>
#include <cuda_fp16.h>
#include <math.h>
#include <stdint.h>

#define NN 100000
#define CC 128
#define EE 1600000
#define HH 4
#define DD 32
#define LL 2

// ---------------- device scratch (allocation-free: static globals) ----------
__device__ int   g_is64;
__device__ int   g_src[EE];
__device__ int   g_dst[EE];
__device__ int   g_srcs[EE];
__device__ int   g_count[NN];
__device__ int   g_rowstart[NN + 2];
__device__ int   g_cursor[NN];
__device__ int   g_bsum[128];
__device__ int   g_bsum2[128];
__device__ __half g_qh[(size_t)NN * 128];      // Q fp16
__device__ __half g_kv[(size_t)NN * 256];      // [n][0:128]=K' fp16  [128:256]=V' fp16
__device__ float g_agg[(size_t)NN * CC];
__device__ float g_h[(size_t)NN * CC];
__device__ float g_b3[384];
__device__ __nv_bfloat16 g_w3bf[384 * 256];    // W3^T split: [n][0:128]=hi [128:256]=lo
__device__ __nv_bfloat16 g_wabf[128 * 256];    // Wa^T split

// ---------------- zero + edge-index dtype detection (fused) ------------------
__global__ void k_zero(const void* ei, int n) {
    int i = blockIdx.x * blockDim.x + threadIdx.x;
    if (i < n) g_count[i] = 0;
    if (blockIdx.x == 0 && threadIdx.x == 0) {
        const long long* q = (const long long*)ei;
        int is64 = 1;
        for (int k = 0; k < 64; k++) {
            long long v = q[k];
            if (v < 0 || v >= NN) { is64 = 0; break; }
        }
        g_is64 = is64;
    }
}

// 2 edges per thread, 16B vector loads
__global__ void k_convert(const void* ei, int E) {
    int t = blockIdx.x * blockDim.x + threadIdx.x;
    int e = t * 2;
    if (e >= E) return;
    bool two = (e + 1 < E);
    int s0, d0, s1 = 0, d1 = 0;
    if (g_is64) {
        const longlong2* ps = (const longlong2*)ei;
        const longlong2* pd = (const longlong2*)((const long long*)ei + E);
        longlong2 sv = ps[t], dv = pd[t];
        s0 = (int)sv.x; s1 = (int)sv.y;
        d0 = (int)dv.x; d1 = (int)dv.y;
    } else {
        const int2* ps = (const int2*)ei;
        const int2* pd = (const int2*)((const int*)ei + E);
        int2 sv = ps[t], dv = pd[t];
        s0 = sv.x; s1 = sv.y;
        d0 = dv.x; d1 = dv.y;
    }
    g_src[e] = s0; g_dst[e] = d0;
    atomicAdd(&g_count[d0], 1);
    if (two) {
        g_src[e + 1] = s1; g_dst[e + 1] = d1;
        atomicAdd(&g_count[d1], 1);
    }
}

// ---------------- counting sort by dst ---------------------------------------
__global__ void k_scan1(int n) {
    __shared__ int sh[1024];
    int i = blockIdx.x * 1024 + threadIdx.x;
    int v = (i < n) ? g_count[i] : 0;
    sh[threadIdx.x] = v;
    __syncthreads();
    for (int off = 1; off < 1024; off <<= 1) {
        int t = (threadIdx.x >= off) ? sh[threadIdx.x - off] : 0;
        __syncthreads();
        sh[threadIdx.x] += t;
        __syncthreads();
    }
    if (i < n) g_rowstart[i] = sh[threadIdx.x] - v;
    if (threadIdx.x == 1023) g_bsum[blockIdx.x] = sh[1023];
}

__global__ void k_scan2(int nb) {
    __shared__ int sh[128];
    int v = (threadIdx.x < nb) ? g_bsum[threadIdx.x] : 0;
    sh[threadIdx.x] = v;
    __syncthreads();
    for (int off = 1; off < 128; off <<= 1) {
        int t = (threadIdx.x >= off) ? sh[threadIdx.x - off] : 0;
        __syncthreads();
        sh[threadIdx.x] += t;
        __syncthreads();
    }
    g_bsum2[threadIdx.x] = sh[threadIdx.x] - v;
}

__global__ void k_scan3(int n, int E) {
    int i = blockIdx.x * blockDim.x + threadIdx.x;
    if (i < n) {
        int r = g_rowstart[i] + g_bsum2[i >> 10];
        g_rowstart[i] = r;
        g_cursor[i] = r;
    }
    if (i == 0) g_rowstart[n] = E;
}

__global__ void k_scatter(int E) {
    int e = blockIdx.x * blockDim.x + threadIdx.x;
    if (e >= E) return;
    int d = g_dst[e];
    int pos = atomicAdd(&g_cursor[d], 1);
    g_srcs[pos] = g_src[e];
}

// ---------------- fold relation transforms -> split transposed bf16 ----------
__global__ void k_fold(const float* __restrict__ Wq, const float* __restrict__ Wk,
                       const float* __restrict__ Wv, const float* __restrict__ bq,
                       const float* __restrict__ bk, const float* __restrict__ bv,
                       const float* __restrict__ a_rel, const float* __restrict__ m_rel,
                       int l) {
    int idx = blockIdx.x * blockDim.x + threadIdx.x;
    if (idx >= CC * 384) return;
    int c = idx / 384, j = idx % 384;
    float val;
    if (j < 128) {
        val = Wq[((size_t)l * CC + c) * CC + j];
    } else {
        int e = (j < 256) ? j - 128 : j - 256;
        int h = e >> 5, ee = e & 31;
        const float* Wx = (j < 256) ? Wk : Wv;
        const float* Rx = (j < 256) ? a_rel : m_rel;
        const float* wrow = Wx + ((size_t)l * CC + c) * CC + h * DD;
        const float* rr = Rx + ((size_t)(l * HH + h) * DD) * DD + ee;
        float s = 0.f;
#pragma unroll
        for (int d = 0; d < DD; d++) s += wrow[d] * rr[d * DD];
        val = s;
    }
    __nv_bfloat16 hi = __float2bfloat16_rn(val);
    __nv_bfloat16 lo = __float2bfloat16_rn(val - __bfloat162float(hi));
    g_w3bf[(size_t)j * 256 + c] = hi;
    g_w3bf[(size_t)j * 256 + 128 + c] = lo;
    if (c == 0) {
        float bval;
        if (j < 128) {
            bval = bq[l * CC + j];
        } else {
            int e = (j < 256) ? j - 128 : j - 256;
            int h = e >> 5, ee = e & 31;
            const float* bx = (j < 256) ? bk : bv;
            const float* Rx = (j < 256) ? a_rel : m_rel;
            float s = 0.f;
#pragma unroll
            for (int d = 0; d < DD; d++)
                s += bx[l * CC + h * DD + d] * Rx[((size_t)(l * HH + h) * DD + d) * DD + ee];
            bval = s;
        }
        g_b3[j] = bval;
    }
}

// ---------------- transpose + hi/lo bf16 split of Wa --------------------------
__global__ void k_wsplit(const float* __restrict__ W, __nv_bfloat16* __restrict__ dst,
                         int Ncols) {
    int idx = blockIdx.x * blockDim.x + threadIdx.x;
    if (idx >= 128 * Ncols) return;
    int n = idx >> 7, k = idx & 127;
    float v = W[(size_t)k * Ncols + n];
    __nv_bfloat16 hi = __float2bfloat16_rn(v);
    __nv_bfloat16 lo = __float2bfloat16_rn(v - __bfloat162float(hi));
    dst[(size_t)n * 256 + k] = hi;
    dst[(size_t)n * 256 + 128 + k] = lo;
}

// ---------------- HMMA (mma.sync) bf16-split GEMM ----------------------------
// CTA tile 128(M) x 128(N), A tile resident; warp tile 32x64 (4m x 2n warps).
// Per k-step: 12 ldsm.x4 -> 48 MMAs (ratio 4). smem 139KB, 1 CTA/SM.
#define LDT 136
#define T128 (128 * LDT * 2)
#define SM_AH 0
#define SM_AL T128
#define SM_BH (2 * T128)
#define SM_BL (3 * T128)
#define SM_FC (4 * T128)
#define SMEM_MMA (SM_FC + 2048)

__device__ __forceinline__ void ldsm_x4(uint32_t& r0, uint32_t& r1, uint32_t& r2,
                                        uint32_t& r3, uint32_t addr) {
    asm volatile("ldmatrix.sync.aligned.m8n8.x4.shared.b16 {%0,%1,%2,%3}, [%4];"
                 : "=r"(r0), "=r"(r1), "=r"(r2), "=r"(r3) : "r"(addr));
}

__device__ __forceinline__ void mma16816(float* d, const uint32_t* a,
                                         uint32_t b0, uint32_t b1) {
    asm volatile(
        "mma.sync.aligned.m16n8k16.row.col.f32.bf16.bf16.f32 "
        "{%0,%1,%2,%3}, {%4,%5,%6,%7}, {%8,%9}, {%0,%1,%2,%3};"
        : "+f"(d[0]), "+f"(d[1]), "+f"(d[2]), "+f"(d[3])
        : "r"(a[0]), "r"(a[1]), "r"(a[2]), "r"(a[3]), "r"(b0), "r"(b1));
}

__device__ __forceinline__ uint32_t pack_bf2(float a, float b) {
    __nv_bfloat162 t = __halves2bfloat162(__float2bfloat16_rn(a), __float2bfloat16_rn(b));
    uint32_t r;
    memcpy(&r, &t, 4);
    return r;
}

#define CP_ASYNC16(dst_u32, src_ptr) \
    asm volatile("cp.async.cg.shared.global [%0], [%1], 16;" \
                 :: "r"(dst_u32), "l"(src_ptr))
#define CP_COMMIT() asm volatile("cp.async.commit_group;" ::: "memory")
#define CP_WAIT0()  asm volatile("cp.async.wait_group 0;" ::: "memory")

template <bool GELU, bool SKIP, bool QKVOUT, bool FC>
__global__ void __launch_bounds__(256, 1) k_hmma(
    const float* __restrict__ A,
    const __nv_bfloat16* __restrict__ Bbf,
    const float* __restrict__ bias,
    float* __restrict__ Cq,
    __half* __restrict__ qh,
    __half* __restrict__ kvout,
    int M,
    const float* __restrict__ hold,
    const float* __restrict__ skipp,
    const float* __restrict__ Wfc,
    const float* __restrict__ bfc,
    float* __restrict__ outp) {
    extern __shared__ __align__(16) char smem[];
    uint32_t smem_base;
    asm("{ .reg .u64 t; cvta.to.shared.u64 t, %1; cvt.u32.u64 %0, t; }"
        : "=r"(smem_base) : "l"(smem));

    int tid = threadIdx.x, wid = tid >> 5, lane = tid & 31;
    int wm = wid & 3, wn = wid >> 2;          // 4m x 2n
    int m0 = blockIdx.x * 128;
    const int NB = QKVOUT ? 3 : 1;            // 128-col B subtiles

    // ---- load A fp32, optional GELU, split hi/lo into smem (once)
#pragma unroll
    for (int it = 0; it < 16; it++) {
        int idx = it * 256 + tid;
        int r = idx >> 5, u = idx & 31;
        int gr = m0 + r;
        if (gr >= M) gr = M - 1;
        float4 v = *(const float4*)&A[(size_t)gr * 128 + u * 4];
        if (GELU) {
            v.x *= normcdff(v.x); v.y *= normcdff(v.y);
            v.z *= normcdff(v.z); v.w *= normcdff(v.w);
        }
        uint32_t h01 = pack_bf2(v.x, v.y), h23 = pack_bf2(v.z, v.w);
        float rx = v.x - __bfloat162float(__float2bfloat16_rn(v.x));
        float ry = v.y - __bfloat162float(__float2bfloat16_rn(v.y));
        float rz = v.z - __bfloat162float(__float2bfloat16_rn(v.z));
        float rw = v.w - __bfloat162float(__float2bfloat16_rn(v.w));
        uint32_t l01 = pack_bf2(rx, ry), l23 = pack_bf2(rz, rw);
        uint32_t off = (uint32_t)(r * LDT + u * 4) * 2;
        *(uint2*)(smem + SM_AH + off) = make_uint2(h01, h23);
        *(uint2*)(smem + SM_AL + off) = make_uint2(l01, l23);
    }

    uint32_t a_off[2], b_off[4];
#pragma unroll
    for (int mi = 0; mi < 2; mi++) {
        int arow = wm * 32 + mi * 16 + (lane & 7) + ((lane >> 3) & 1) * 8;
        int akc = (lane >> 4) * 8;
        a_off[mi] = (uint32_t)(arow * LDT + akc) * 2;
    }
#pragma unroll
    for (int p = 0; p < 4; p++) {
        int nrow = wn * 64 + p * 16 + (lane >> 4) * 8 + (lane & 7);
        int bkc = ((lane >> 3) & 1) * 8;
        b_off[p] = (uint32_t)(nrow * LDT + bkc) * 2;
    }

    int groupID = lane >> 2, tg = lane & 3;
    float g = 0.f, og = 0.f;
    if (SKIP) {
        g = 1.f / (1.f + __expf(-skipp[0]));
        og = 1.f - g;
    }
    float fc0[2][2], fc1[2][2];
    if (FC) {
#pragma unroll
        for (int mi = 0; mi < 2; mi++)
#pragma unroll
            for (int hh = 0; hh < 2; hh++) { fc0[mi][hh] = 0.f; fc1[mi][hh] = 0.f; }
    }

    for (int bt = 0; bt < NB; bt++) {
        int n0 = bt * 128;
        __syncthreads();
        // ---- B subtile via cp.async: 128 rows x 512B (hi|lo)
        {
            const char* Bb = (const char*)Bbf;
#pragma unroll
            for (int it = 0; it < 16; it++) {
                int idx = it * 256 + tid;
                int r = idx >> 5, u = idx & 31;
                const char* src = Bb + (size_t)(n0 + r) * 512 + u * 16;
                uint32_t dst = smem_base + (u < 16 ? SM_BH : SM_BL)
                             + (uint32_t)(r * LDT + (u & 15) * 8) * 2;
                CP_ASYNC16(dst, src);
            }
            CP_COMMIT();
            CP_WAIT0();
        }
        __syncthreads();

        float acc[2][8][4];
#pragma unroll
        for (int mi = 0; mi < 2; mi++)
#pragma unroll
            for (int ni = 0; ni < 8; ni++)
#pragma unroll
                for (int c = 0; c < 4; c++) acc[mi][ni][c] = 0.f;

        // ---- mainloop: 12 ldsm.x4 -> 48 MMAs per k-step, staged for low live regs
#pragma unroll
        for (int ks = 0; ks < 8; ks++) {
            uint32_t kb = (uint32_t)ks * 32;
            uint32_t ah[2][4], bh[8][2];
#pragma unroll
            for (int mi = 0; mi < 2; mi++)
                ldsm_x4(ah[mi][0], ah[mi][1], ah[mi][2], ah[mi][3],
                        smem_base + SM_AH + a_off[mi] + kb);
#pragma unroll
            for (int p = 0; p < 4; p++) {
                uint32_t r0, r1, r2, r3;
                ldsm_x4(r0, r1, r2, r3, smem_base + SM_BH + b_off[p] + kb);
                bh[p * 2][0] = r0; bh[p * 2][1] = r1;
                bh[p * 2 + 1][0] = r2; bh[p * 2 + 1][1] = r3;
            }
#pragma unroll
            for (int mi = 0; mi < 2; mi++)
#pragma unroll
                for (int ni = 0; ni < 8; ni++)
                    mma16816(acc[mi][ni], ah[mi], bh[ni][0], bh[ni][1]);
            // Al x Bh
            {
                uint32_t al[2][4];
#pragma unroll
                for (int mi = 0; mi < 2; mi++)
                    ldsm_x4(al[mi][0], al[mi][1], al[mi][2], al[mi][3],
                            smem_base + SM_AL + a_off[mi] + kb);
#pragma unroll
                for (int mi = 0; mi < 2; mi++)
#pragma unroll
                    for (int ni = 0; ni < 8; ni++)
                        mma16816(acc[mi][ni], al[mi], bh[ni][0], bh[ni][1]);
            }
            // Ah x Bl
            {
                uint32_t bl[8][2];
#pragma unroll
                for (int p = 0; p < 4; p++) {
                    uint32_t r0, r1, r2, r3;
                    ldsm_x4(r0, r1, r2, r3, smem_base + SM_BL + b_off[p] + kb);
                    bl[p * 2][0] = r0; bl[p * 2][1] = r1;
                    bl[p * 2 + 1][0] = r2; bl[p * 2 + 1][1] = r3;
                }
#pragma unroll
                for (int mi = 0; mi < 2; mi++)
#pragma unroll
                    for (int ni = 0; ni < 8; ni++)
                        mma16816(acc[mi][ni], ah[mi], bl[ni][0], bl[ni][1]);
            }
        }

        // ---- epilogue
#pragma unroll
        for (int mi = 0; mi < 2; mi++) {
#pragma unroll
            for (int hh = 0; hh < 2; hh++) {
                int row = m0 + wm * 32 + mi * 16 + groupID + hh * 8;
                bool rok = row < M;
#pragma unroll
                for (int ni = 0; ni < 8; ni++) {
                    int col = n0 + wn * 64 + ni * 8 + tg * 2;
                    float v0 = acc[mi][ni][hh * 2]     + bias[col];
                    float v1 = acc[mi][ni][hh * 2 + 1] + bias[col + 1];
                    if (QKVOUT) {
                        if (rok) {
                            __half2 hv2 = __floats2half2_rn(v0, v1);
                            uint32_t bits; memcpy(&bits, &hv2, 4);
                            if (bt == 0)
                                *(uint32_t*)&qh[(size_t)row * 128 + col] = bits;
                            else
                                *(uint32_t*)&kvout[(size_t)row * 256 + (col - 128)] = bits;
                        }
                    } else {
                        if (SKIP) {
                            float2 hv = *(const float2*)&hold[(size_t)row * 128 + col];
                            v0 = g * v0 + og * hv.x;
                            v1 = g * v1 + og * hv.y;
                        }
                        if (!FC) {
                            if (rok) {
                                float2 o; o.x = v0; o.y = v1;
                                *(float2*)&Cq[(size_t)row * 128 + col] = o;
                            }
                        } else {
                            fc0[mi][hh] += v0 * Wfc[col * 2]     + v1 * Wfc[col * 2 + 2];
                            fc1[mi][hh] += v0 * Wfc[col * 2 + 1] + v1 * Wfc[col * 2 + 3];
                        }
                    }
                }
            }
        }
    }

    if (FC) {
        float* fcbuf = (float*)(smem + SM_FC);   // [2 wn][128 row][2]
#pragma unroll
        for (int mi = 0; mi < 2; mi++) {
#pragma unroll
            for (int hh = 0; hh < 2; hh++) {
                float a0 = fc0[mi][hh], a1 = fc1[mi][hh];
                a0 += __shfl_xor_sync(0xffffffffu, a0, 1);
                a0 += __shfl_xor_sync(0xffffffffu, a0, 2);
                a1 += __shfl_xor_sync(0xffffffffu, a1, 1);
                a1 += __shfl_xor_sync(0xffffffffu, a1, 2);
                int rowl = wm * 32 + mi * 16 + groupID + hh * 8;
                if (tg == 0) {
                    fcbuf[(wn * 128 + rowl) * 2]     = a0;
                    fcbuf[(wn * 128 + rowl) * 2 + 1] = a1;
                }
            }
        }
        __syncthreads();
        if (tid < 128) {
            int gr = m0 + tid;
            if (gr < M) {
                float o0 = fcbuf[tid * 2]     + fcbuf[(128 + tid) * 2]     + bfc[0];
                float o1 = fcbuf[tid * 2 + 1] + fcbuf[(128 + tid) * 2 + 1] + bfc[1];
                outp[(size_t)gr * 2]     = o0;
                outp[(size_t)gr * 2 + 1] = o1;
            }
        }
    }
}

// ---------------- edge phase: one warp per dst node, 4-edge batched -----------
__global__ void __launch_bounds__(256) k_edge(const float* __restrict__ prel) {
    int w = (blockIdx.x * blockDim.x + threadIdx.x) >> 5;
    int lane = threadIdx.x & 31;
    if (w >= NN) return;
    int r0 = g_rowstart[w], r1 = g_rowstart[w + 1];
    int h = lane >> 3;
    uint2 qb = __ldcs((const uint2*)&g_qh[(size_t)w * 128 + lane * 4]);
    __half2 qh0, qh1;
    memcpy(&qh0, &qb.x, 4); memcpy(&qh1, &qb.y, 4);
    float2 qf0 = __half22float2(qh0), qf1 = __half22float2(qh1);
    const float4 q4 = {qf0.x, qf0.y, qf1.x, qf1.y};
    const float scale = prel[h] * 0.17677669529663687f;
    float denom = 0.f;
    float4 acc = {0.f, 0.f, 0.f, 0.f};

    int j = r0;
    for (; j + 4 <= r1; j += 4) {
        int s[4];
#pragma unroll
        for (int u = 0; u < 4; u++) s[u] = __ldcs(&g_srcs[j + u]);
        uint2 kb[4], vb[4];
#pragma unroll
        for (int u = 0; u < 4; u++) {
            kb[u] = *(const uint2*)&g_kv[(size_t)s[u] * 256 + lane * 4];
            vb[u] = *(const uint2*)&g_kv[(size_t)s[u] * 256 + 128 + lane * 4];
        }
        float ev[4];
#pragma unroll
        for (int u = 0; u < 4; u++) {
            __half2 k0, k1;
            memcpy(&k0, &kb[u].x, 4); memcpy(&k1, &kb[u].y, 4);
            float2 kf0 = __half22float2(k0), kf1 = __half22float2(k1);
            float p = q4.x * kf0.x + q4.y * kf0.y + q4.z * kf1.x + q4.w * kf1.y;
            p += __shfl_xor_sync(0xffffffffu, p, 1);
            p += __shfl_xor_sync(0xffffffffu, p, 2);
            p += __shfl_xor_sync(0xffffffffu, p, 4);
            ev[u] = __expf(p * scale);
        }
#pragma unroll
        for (int u = 0; u < 4; u++) {
            __half2 v0, v1;
            memcpy(&v0, &vb[u].x, 4); memcpy(&v1, &vb[u].y, 4);
            float2 vf0 = __half22float2(v0), vf1 = __half22float2(v1);
            denom += ev[u];
            acc.x += ev[u] * vf0.x;
            acc.y += ev[u] * vf0.y;
            acc.z += ev[u] * vf1.x;
            acc.w += ev[u] * vf1.y;
        }
    }
    for (; j < r1; j++) {
        int s = __ldcs(&g_srcs[j]);
        uint2 kbits = *(const uint2*)&g_kv[(size_t)s * 256 + lane * 4];
        uint2 vbits = *(const uint2*)&g_kv[(size_t)s * 256 + 128 + lane * 4];
        __half2 k0, k1, v0, v1;
        memcpy(&k0, &kbits.x, 4); memcpy(&k1, &kbits.y, 4);
        memcpy(&v0, &vbits.x, 4); memcpy(&v1, &vbits.y, 4);
        float2 kf0 = __half22float2(k0), kf1 = __half22float2(k1);
        float p = q4.x * kf0.x + q4.y * kf0.y + q4.z * kf1.x + q4.w * kf1.y;
        p += __shfl_xor_sync(0xffffffffu, p, 1);
        p += __shfl_xor_sync(0xffffffffu, p, 2);
        p += __shfl_xor_sync(0xffffffffu, p, 4);
        float ev = __expf(p * scale);
        denom += ev;
        float2 vf0 = __half22float2(v0), vf1 = __half22float2(v1);
        acc.x += ev * vf0.x;
        acc.y += ev * vf0.y;
        acc.z += ev * vf1.x;
        acc.w += ev * vf1.y;
    }
    float inv = (r1 > r0) ? 1.f / denom : 0.f;
    acc.x *= inv; acc.y *= inv; acc.z *= inv; acc.w *= inv;
    __stcs((float4*)&g_agg[(size_t)w * CC + lane * 4], acc);
}

// -----------------------------------------------------------------------------
extern "C" void kernel_launch(void* const* d_in, const int* in_sizes, int n_in,
                              void* d_out, int out_size) {
    const float* x     = (const float*)d_in[0];
    const void*  ei    = d_in[1];
    const float* Wk    = (const float*)d_in[2];
    const float* bk    = (const float*)d_in[3];
    const float* Wq    = (const float*)d_in[4];
    const float* bq    = (const float*)d_in[5];
    const float* Wv    = (const float*)d_in[6];
    const float* bv    = (const float*)d_in[7];
    const float* a_rel = (const float*)d_in[8];
    const float* m_rel = (const float*)d_in[9];
    const float* p_rel = (const float*)d_in[10];
    const float* Wa    = (const float*)d_in[11];
    const float* ba    = (const float*)d_in[12];
    const float* skip  = (const float*)d_in[13];
    const float* Wfc   = (const float*)d_in[14];
    const float* bfc   = (const float*)d_in[15];
    float* out = (float*)d_out;

    int E = in_sizes[1] / 2;
    if (E > EE) E = EE;

    float *p_h, *p_agg, *p_b3;
    __half *p_qh, *p_kv;
    __nv_bfloat16 *p_w3bf, *p_wabf;
    cudaGetSymbolAddress((void**)&p_h, g_h);
    cudaGetSymbolAddress((void**)&p_agg, g_agg);
    cudaGetSymbolAddress((void**)&p_qh, g_qh);
    cudaGetSymbolAddress((void**)&p_kv, g_kv);
    cudaGetSymbolAddress((void**)&p_b3, g_b3);
    cudaGetSymbolAddress((void**)&p_w3bf, g_w3bf);
    cudaGetSymbolAddress((void**)&p_wabf, g_wabf);

    cudaFuncSetAttribute(k_hmma<false, false, true, false>,
                         cudaFuncAttributeMaxDynamicSharedMemorySize, SMEM_MMA);
    cudaFuncSetAttribute(k_hmma<true, true, false, false>,
                         cudaFuncAttributeMaxDynamicSharedMemorySize, SMEM_MMA);
    cudaFuncSetAttribute(k_hmma<true, true, false, true>,
                         cudaFuncAttributeMaxDynamicSharedMemorySize, SMEM_MMA);

    int eb2 = (E / 2 + 255) / 256;
    int eb = (E + 255) / 256;
    int nb1024 = (NN + 1023) / 1024;
    int mtiles = (NN + 127) / 128;          // 782
    int sgrid = (NN * 32 + 255) / 256;      // 12500

    k_zero<<<(NN + 255) / 256, 256>>>(ei, NN);                 // 1
    k_convert<<<eb2, 256>>>(ei, E);                            // 2
    k_fold<<<(CC * 384 + 255) / 256, 256>>>(Wq, Wk, Wv, bq, bk, bv, a_rel, m_rel, 0); // 3
    k_hmma<false, false, true, false><<<mtiles, 256, SMEM_MMA>>>(                     // 4
        x, p_w3bf, p_b3, nullptr, p_qh, p_kv, NN,
        nullptr, nullptr, nullptr, nullptr, nullptr);
    k_wsplit<<<(128 * 128 + 255) / 256, 256>>>(Wa, p_wabf, 128);                      // 5
    k_scan1<<<nb1024, 1024>>>(NN);                             // 6
    k_scan2<<<1, 128>>>(nb1024);                               // 7
    k_scan3<<<(NN + 255) / 256, 256>>>(NN, E);                 // 8
    k_scatter<<<eb, 256>>>(E);                                 // 9

    k_edge<<<sgrid, 256>>>(p_rel);                             // 10
    k_hmma<true, true, false, false><<<mtiles, 256, SMEM_MMA>>>(                      // 11
        p_agg, p_wabf, ba, p_h, nullptr, nullptr, NN,
        x, skip, nullptr, nullptr, nullptr);

    k_fold<<<(CC * 384 + 255) / 256, 256>>>(Wq, Wk, Wv, bq, bk, bv, a_rel, m_rel, 1); // 12
    k_wsplit<<<(128 * 128 + 255) / 256, 256>>>(Wa + (size_t)CC * CC, p_wabf, 128);    // 13
    k_hmma<false, false, true, false><<<mtiles, 256, SMEM_MMA>>>(                     // 14
        p_h, p_w3bf, p_b3, nullptr, p_qh, p_kv, NN,
        nullptr, nullptr, nullptr, nullptr, nullptr);
    k_edge<<<sgrid, 256>>>(p_rel + HH);                        // 15
    k_hmma<true, true, false, true><<<mtiles, 256, SMEM_MMA>>>(                       // 16
        p_agg, p_wabf, ba + CC, nullptr, nullptr, nullptr, NN,
        p_h, skip + 1, Wfc, bfc, out);
}

// round 12
// speedup vs baseline: 1.2859x; 1.2859x over previous
#include <cuda_runtime.h>
#include <cuda_bf16.h>
#include <cuda_fp16.h>
#include <math.h>
#include <stdint.h>

#define NN 100000
#define CC 128
#define EE 1600000
#define HH 4
#define DD 32
#define LL 2

// ---------------- device scratch (allocation-free: static globals) ----------
__device__ int   g_is64;
__device__ int   g_src[EE];
__device__ int   g_dst[EE];
__device__ int   g_srcs[EE];
__device__ int   g_count[NN];
__device__ int   g_rowstart[NN + 2];
__device__ int   g_cursor[NN];
__device__ int   g_bsum[128];
__device__ int   g_bsum2[128];
__device__ __half g_qh[(size_t)NN * 128];      // Q fp16
__device__ __half g_kv[(size_t)NN * 256];      // [n][0:128]=K' fp16  [128:256]=V' fp16
__device__ float g_agg[(size_t)NN * CC];
__device__ float g_h[(size_t)NN * CC];
__device__ float g_b3[384];
__device__ __half g_w3h[384 * 128];            // W3^T fp16: [n][c]
__device__ __nv_bfloat16 g_wabf[128 * 256];    // Wa^T split: [n][0:128]=hi [128:256]=lo

// ---------------- zero + edge-index dtype detection (fused) ------------------
__global__ void k_zero(const void* ei, int n) {
    int i = blockIdx.x * blockDim.x + threadIdx.x;
    if (i < n) g_count[i] = 0;
    if (blockIdx.x == 0 && threadIdx.x == 0) {
        const long long* q = (const long long*)ei;
        int is64 = 1;
        for (int k = 0; k < 64; k++) {
            long long v = q[k];
            if (v < 0 || v >= NN) { is64 = 0; break; }
        }
        g_is64 = is64;
    }
}

// 2 edges per thread, 16B vector loads
__global__ void k_convert(const void* ei, int E) {
    int t = blockIdx.x * blockDim.x + threadIdx.x;
    int e = t * 2;
    if (e >= E) return;
    bool two = (e + 1 < E);
    int s0, d0, s1 = 0, d1 = 0;
    if (g_is64) {
        const longlong2* ps = (const longlong2*)ei;
        const longlong2* pd = (const longlong2*)((const long long*)ei + E);
        longlong2 sv = ps[t], dv = pd[t];
        s0 = (int)sv.x; s1 = (int)sv.y;
        d0 = (int)dv.x; d1 = (int)dv.y;
    } else {
        const int2* ps = (const int2*)ei;
        const int2* pd = (const int2*)((const int*)ei + E);
        int2 sv = ps[t], dv = pd[t];
        s0 = sv.x; s1 = sv.y;
        d0 = dv.x; d1 = dv.y;
    }
    g_src[e] = s0; g_dst[e] = d0;
    atomicAdd(&g_count[d0], 1);
    if (two) {
        g_src[e + 1] = s1; g_dst[e + 1] = d1;
        atomicAdd(&g_count[d1], 1);
    }
}

// ---------------- counting sort by dst ---------------------------------------
__global__ void k_scan1(int n) {
    __shared__ int sh[1024];
    int i = blockIdx.x * 1024 + threadIdx.x;
    int v = (i < n) ? g_count[i] : 0;
    sh[threadIdx.x] = v;
    __syncthreads();
    for (int off = 1; off < 1024; off <<= 1) {
        int t = (threadIdx.x >= off) ? sh[threadIdx.x - off] : 0;
        __syncthreads();
        sh[threadIdx.x] += t;
        __syncthreads();
    }
    if (i < n) g_rowstart[i] = sh[threadIdx.x] - v;
    if (threadIdx.x == 1023) g_bsum[blockIdx.x] = sh[1023];
}

__global__ void k_scan2(int nb) {
    __shared__ int sh[128];
    int v = (threadIdx.x < nb) ? g_bsum[threadIdx.x] : 0;
    sh[threadIdx.x] = v;
    __syncthreads();
    for (int off = 1; off < 128; off <<= 1) {
        int t = (threadIdx.x >= off) ? sh[threadIdx.x - off] : 0;
        __syncthreads();
        sh[threadIdx.x] += t;
        __syncthreads();
    }
    g_bsum2[threadIdx.x] = sh[threadIdx.x] - v;
}

__global__ void k_scan3(int n, int E) {
    int i = blockIdx.x * blockDim.x + threadIdx.x;
    if (i < n) {
        int r = g_rowstart[i] + g_bsum2[i >> 10];
        g_rowstart[i] = r;
        g_cursor[i] = r;
    }
    if (i == 0) g_rowstart[n] = E;
}

__global__ void k_scatter(int E) {
    int e = blockIdx.x * blockDim.x + threadIdx.x;
    if (e >= E) return;
    int d = g_dst[e];
    int pos = atomicAdd(&g_cursor[d], 1);
    g_srcs[pos] = g_src[e];
}

// ---------------- fold relation transforms -> transposed fp16 W3 -------------
__global__ void k_fold(const float* __restrict__ Wq, const float* __restrict__ Wk,
                       const float* __restrict__ Wv, const float* __restrict__ bq,
                       const float* __restrict__ bk, const float* __restrict__ bv,
                       const float* __restrict__ a_rel, const float* __restrict__ m_rel,
                       int l) {
    int idx = blockIdx.x * blockDim.x + threadIdx.x;
    if (idx >= CC * 384) return;
    int c = idx / 384, j = idx % 384;
    float val;
    if (j < 128) {
        val = Wq[((size_t)l * CC + c) * CC + j];
    } else {
        int e = (j < 256) ? j - 128 : j - 256;
        int h = e >> 5, ee = e & 31;
        const float* Wx = (j < 256) ? Wk : Wv;
        const float* Rx = (j < 256) ? a_rel : m_rel;
        const float* wrow = Wx + ((size_t)l * CC + c) * CC + h * DD;
        const float* rr = Rx + ((size_t)(l * HH + h) * DD) * DD + ee;
        float s = 0.f;
#pragma unroll
        for (int d = 0; d < DD; d++) s += wrow[d] * rr[d * DD];
        val = s;
    }
    g_w3h[(size_t)j * 128 + c] = __float2half_rn(val);
    if (c == 0) {
        float bval;
        if (j < 128) {
            bval = bq[l * CC + j];
        } else {
            int e = (j < 256) ? j - 128 : j - 256;
            int h = e >> 5, ee = e & 31;
            const float* bx = (j < 256) ? bk : bv;
            const float* Rx = (j < 256) ? a_rel : m_rel;
            float s = 0.f;
#pragma unroll
            for (int d = 0; d < DD; d++)
                s += bx[l * CC + h * DD + d] * Rx[((size_t)(l * HH + h) * DD + d) * DD + ee];
            bval = s;
        }
        g_b3[j] = bval;
    }
}

// ---------------- transpose + hi/lo bf16 split of Wa --------------------------
__global__ void k_wsplit(const float* __restrict__ W, __nv_bfloat16* __restrict__ dst,
                         int Ncols) {
    int idx = blockIdx.x * blockDim.x + threadIdx.x;
    if (idx >= 128 * Ncols) return;
    int n = idx >> 7, k = idx & 127;
    float v = W[(size_t)k * Ncols + n];
    __nv_bfloat16 hi = __float2bfloat16_rn(v);
    __nv_bfloat16 lo = __float2bfloat16_rn(v - __bfloat162float(hi));
    dst[(size_t)n * 256 + k] = hi;
    dst[(size_t)n * 256 + 128 + k] = lo;
}

// ================= shared GEMM helpers ========================================
#define LDT 136

__device__ __forceinline__ void ldsm_x4(uint32_t& r0, uint32_t& r1, uint32_t& r2,
                                        uint32_t& r3, uint32_t addr) {
    asm volatile("ldmatrix.sync.aligned.m8n8.x4.shared.b16 {%0,%1,%2,%3}, [%4];"
                 : "=r"(r0), "=r"(r1), "=r"(r2), "=r"(r3) : "r"(addr));
}

__device__ __forceinline__ void mma16816_bf(float* d, const uint32_t* a,
                                            uint32_t b0, uint32_t b1) {
    asm volatile(
        "mma.sync.aligned.m16n8k16.row.col.f32.bf16.bf16.f32 "
        "{%0,%1,%2,%3}, {%4,%5,%6,%7}, {%8,%9}, {%0,%1,%2,%3};"
        : "+f"(d[0]), "+f"(d[1]), "+f"(d[2]), "+f"(d[3])
        : "r"(a[0]), "r"(a[1]), "r"(a[2]), "r"(a[3]), "r"(b0), "r"(b1));
}

__device__ __forceinline__ void mma16816_f16(float* d, const uint32_t* a,
                                             uint32_t b0, uint32_t b1) {
    asm volatile(
        "mma.sync.aligned.m16n8k16.row.col.f32.f16.f16.f32 "
        "{%0,%1,%2,%3}, {%4,%5,%6,%7}, {%8,%9}, {%0,%1,%2,%3};"
        : "+f"(d[0]), "+f"(d[1]), "+f"(d[2]), "+f"(d[3])
        : "r"(a[0]), "r"(a[1]), "r"(a[2]), "r"(a[3]), "r"(b0), "r"(b1));
}

__device__ __forceinline__ uint32_t pack_bf2(float a, float b) {
    __nv_bfloat162 t = __halves2bfloat162(__float2bfloat16_rn(a), __float2bfloat16_rn(b));
    uint32_t r;
    memcpy(&r, &t, 4);
    return r;
}

#define CP_ASYNC16(dst_u32, src_ptr) \
    asm volatile("cp.async.cg.shared.global [%0], [%1], 16;" \
                 :: "r"(dst_u32), "l"(src_ptr))
#define CP_COMMIT() asm volatile("cp.async.commit_group;" ::: "memory")
#define CP_WAIT0()  asm volatile("cp.async.wait_group 0;" ::: "memory")

// ---------------- QKV GEMM: single-pass fp16 ----------------------------------
// [Q|K'|V'] = A_fp32 @ W3_fp16; outputs all fp16 (output quantization dominates,
// so fp16 inputs cost ~nothing extra in precision). CTA tile 128(M) x 64(N),
// NB=6 subtiles. smem 52KB -> 4 CTAs/SM. Warp tile 32x32, 1 segment.
#define QK_A (128 * LDT * 2)
#define QK_B (64 * LDT * 2)
#define SMEM_QKV (QK_A + QK_B)

__global__ void __launch_bounds__(256, 2) k_qkv(
    const float* __restrict__ A,
    const __half* __restrict__ W,      // [384][128] fp16, n-major
    const float* __restrict__ bias,
    __half* __restrict__ qh,
    __half* __restrict__ kvout,
    int M) {
    extern __shared__ __align__(16) char smem[];
    uint32_t smem_base;
    asm("{ .reg .u64 t; cvta.to.shared.u64 t, %1; cvt.u32.u64 %0, t; }"
        : "=r"(smem_base) : "l"(smem));

    int tid = threadIdx.x, wid = tid >> 5, lane = tid & 31;
    int wm = wid & 3, wn = wid >> 2;
    int m0 = blockIdx.x * 128;

    // ---- A fp32 -> fp16 into smem (once)
#pragma unroll
    for (int it = 0; it < 16; it++) {
        int idx = it * 256 + tid;
        int r = idx >> 5, u = idx & 31;
        int gr = m0 + r;
        if (gr >= M) gr = M - 1;
        float4 v = *(const float4*)&A[(size_t)gr * 128 + u * 4];
        __half2 h0 = __floats2half2_rn(v.x, v.y);
        __half2 h1 = __floats2half2_rn(v.z, v.w);
        uint32_t b0, b1;
        memcpy(&b0, &h0, 4); memcpy(&b1, &h1, 4);
        *(uint2*)(smem + (uint32_t)(r * LDT + u * 4) * 2) = make_uint2(b0, b1);
    }

    uint32_t a_off[2], b_off[2];
#pragma unroll
    for (int mi = 0; mi < 2; mi++) {
        int arow = wm * 32 + mi * 16 + (lane & 7) + ((lane >> 3) & 1) * 8;
        int akc = (lane >> 4) * 8;
        a_off[mi] = (uint32_t)(arow * LDT + akc) * 2;
    }
#pragma unroll
    for (int p = 0; p < 2; p++) {
        int nrow = wn * 32 + p * 16 + (lane >> 4) * 8 + (lane & 7);
        int bkc = ((lane >> 3) & 1) * 8;
        b_off[p] = (uint32_t)(nrow * LDT + bkc) * 2;
    }
    int groupID = lane >> 2, tg = lane & 3;

    for (int bt = 0; bt < 6; bt++) {
        int n0 = bt * 64;
        __syncthreads();
        // ---- B subtile via cp.async: 64 rows x 256B
        {
            const char* Wb = (const char*)W;
#pragma unroll
            for (int it = 0; it < 4; it++) {
                int idx = it * 256 + tid;
                int r = idx >> 4, u = idx & 15;
                const char* src = Wb + (size_t)(n0 + r) * 256 + u * 16;
                uint32_t dst = smem_base + QK_A + (uint32_t)(r * LDT + u * 8) * 2;
                CP_ASYNC16(dst, src);
            }
            CP_COMMIT();
            CP_WAIT0();
        }
        __syncthreads();

        float acc[2][4][4];
#pragma unroll
        for (int mi = 0; mi < 2; mi++)
#pragma unroll
            for (int ni = 0; ni < 4; ni++)
#pragma unroll
                for (int c = 0; c < 4; c++) acc[mi][ni][c] = 0.f;

#pragma unroll
        for (int ks = 0; ks < 8; ks++) {
            uint32_t kb = (uint32_t)ks * 32;
            uint32_t a[2][4], b[4][2];
#pragma unroll
            for (int mi = 0; mi < 2; mi++)
                ldsm_x4(a[mi][0], a[mi][1], a[mi][2], a[mi][3],
                        smem_base + a_off[mi] + kb);
#pragma unroll
            for (int p = 0; p < 2; p++) {
                uint32_t r0, r1, r2, r3;
                ldsm_x4(r0, r1, r2, r3, smem_base + QK_A + b_off[p] + kb);
                b[p * 2][0] = r0; b[p * 2][1] = r1;
                b[p * 2 + 1][0] = r2; b[p * 2 + 1][1] = r3;
            }
#pragma unroll
            for (int mi = 0; mi < 2; mi++)
#pragma unroll
                for (int ni = 0; ni < 4; ni++)
                    mma16816_f16(acc[mi][ni], a[mi], b[ni][0], b[ni][1]);
        }

        // ---- epilogue: fp16 out
#pragma unroll
        for (int mi = 0; mi < 2; mi++) {
#pragma unroll
            for (int hh = 0; hh < 2; hh++) {
                int row = m0 + wm * 32 + mi * 16 + groupID + hh * 8;
                if (row >= M) continue;
#pragma unroll
                for (int ni = 0; ni < 4; ni++) {
                    int col = n0 + wn * 32 + ni * 8 + tg * 2;
                    float v0 = acc[mi][ni][hh * 2]     + bias[col];
                    float v1 = acc[mi][ni][hh * 2 + 1] + bias[col + 1];
                    __half2 hv2 = __floats2half2_rn(v0, v1);
                    uint32_t bits; memcpy(&bits, &hv2, 4);
                    if (bt < 2)
                        *(uint32_t*)&qh[(size_t)row * 128 + col] = bits;
                    else
                        *(uint32_t*)&kvout[(size_t)row * 256 + (col - 128)] = bits;
                }
            }
        }
    }
}

// ---------------- output GEMM: bf16 2-term split (R10 config) -----------------
// CTA tile 128(M) x 64(N), NB=2; smem 104KB -> 2 CTAs/SM; 8 ldsm -> 24 MMA/kstep.
#define A_TILE (128 * LDT * 2)
#define B_TILE (64 * LDT * 2)
#define SM_AH 0
#define SM_AL A_TILE
#define SM_BH (2 * A_TILE)
#define SM_BL (2 * A_TILE + B_TILE)
#define SM_FC (2 * A_TILE + 2 * B_TILE)
#define SMEM_MMA (SM_FC + 2048)

template <bool FC>
__global__ void __launch_bounds__(256, 2) k_hmma(
    const float* __restrict__ A,
    const __nv_bfloat16* __restrict__ Bbf,
    const float* __restrict__ bias,
    float* __restrict__ Cq,
    int M,
    const float* __restrict__ hold,
    const float* __restrict__ skipp,
    const float* __restrict__ Wfc,
    const float* __restrict__ bfc,
    float* __restrict__ outp) {
    extern __shared__ __align__(16) char smem[];
    uint32_t smem_base;
    asm("{ .reg .u64 t; cvta.to.shared.u64 t, %1; cvt.u32.u64 %0, t; }"
        : "=r"(smem_base) : "l"(smem));

    int tid = threadIdx.x, wid = tid >> 5, lane = tid & 31;
    int wm = wid & 3, wn = wid >> 2;
    int m0 = blockIdx.x * 128;

    // ---- load A fp32, GELU, split hi/lo into smem (once)
#pragma unroll
    for (int it = 0; it < 16; it++) {
        int idx = it * 256 + tid;
        int r = idx >> 5, u = idx & 31;
        int gr = m0 + r;
        if (gr >= M) gr = M - 1;
        float4 v = *(const float4*)&A[(size_t)gr * 128 + u * 4];
        v.x *= normcdff(v.x); v.y *= normcdff(v.y);
        v.z *= normcdff(v.z); v.w *= normcdff(v.w);
        uint32_t h01 = pack_bf2(v.x, v.y), h23 = pack_bf2(v.z, v.w);
        float rx = v.x - __bfloat162float(__float2bfloat16_rn(v.x));
        float ry = v.y - __bfloat162float(__float2bfloat16_rn(v.y));
        float rz = v.z - __bfloat162float(__float2bfloat16_rn(v.z));
        float rw = v.w - __bfloat162float(__float2bfloat16_rn(v.w));
        uint32_t l01 = pack_bf2(rx, ry), l23 = pack_bf2(rz, rw);
        uint32_t off = (uint32_t)(r * LDT + u * 4) * 2;
        *(uint2*)(smem + SM_AH + off) = make_uint2(h01, h23);
        *(uint2*)(smem + SM_AL + off) = make_uint2(l01, l23);
    }

    uint32_t a_off[2], b_off[2];
#pragma unroll
    for (int mi = 0; mi < 2; mi++) {
        int arow = wm * 32 + mi * 16 + (lane & 7) + ((lane >> 3) & 1) * 8;
        int akc = (lane >> 4) * 8;
        a_off[mi] = (uint32_t)(arow * LDT + akc) * 2;
    }
#pragma unroll
    for (int p = 0; p < 2; p++) {
        int nrow = wn * 32 + p * 16 + (lane >> 4) * 8 + (lane & 7);
        int bkc = ((lane >> 3) & 1) * 8;
        b_off[p] = (uint32_t)(nrow * LDT + bkc) * 2;
    }

    int groupID = lane >> 2, tg = lane & 3;
    float g = 1.f / (1.f + __expf(-skipp[0]));
    float og = 1.f - g;
    float fc0[2][2], fc1[2][2];
    if (FC) {
#pragma unroll
        for (int mi = 0; mi < 2; mi++)
#pragma unroll
            for (int hh = 0; hh < 2; hh++) { fc0[mi][hh] = 0.f; fc1[mi][hh] = 0.f; }
    }

    for (int bt = 0; bt < 2; bt++) {
        int n0 = bt * 64;
        __syncthreads();
        {
            const char* Bb = (const char*)Bbf;
#pragma unroll
            for (int it = 0; it < 8; it++) {
                int idx = it * 256 + tid;
                int r = idx >> 5, u = idx & 31;
                const char* src = Bb + (size_t)(n0 + r) * 512 + u * 16;
                uint32_t dst = smem_base + (u < 16 ? SM_BH : SM_BL)
                             + (uint32_t)(r * LDT + (u & 15) * 8) * 2;
                CP_ASYNC16(dst, src);
            }
            CP_COMMIT();
            CP_WAIT0();
        }
        __syncthreads();

        float acc[2][4][4];
#pragma unroll
        for (int mi = 0; mi < 2; mi++)
#pragma unroll
            for (int ni = 0; ni < 4; ni++)
#pragma unroll
                for (int c = 0; c < 4; c++) acc[mi][ni][c] = 0.f;

#pragma unroll
        for (int ks = 0; ks < 8; ks++) {
            uint32_t kb = (uint32_t)ks * 32;
            uint32_t ah[2][4], al[2][4], bh[4][2], bl[4][2];
#pragma unroll
            for (int mi = 0; mi < 2; mi++) {
                ldsm_x4(ah[mi][0], ah[mi][1], ah[mi][2], ah[mi][3],
                        smem_base + SM_AH + a_off[mi] + kb);
                ldsm_x4(al[mi][0], al[mi][1], al[mi][2], al[mi][3],
                        smem_base + SM_AL + a_off[mi] + kb);
            }
#pragma unroll
            for (int p = 0; p < 2; p++) {
                uint32_t r0, r1, r2, r3;
                ldsm_x4(r0, r1, r2, r3, smem_base + SM_BH + b_off[p] + kb);
                bh[p * 2][0] = r0; bh[p * 2][1] = r1;
                bh[p * 2 + 1][0] = r2; bh[p * 2 + 1][1] = r3;
                ldsm_x4(r0, r1, r2, r3, smem_base + SM_BL + b_off[p] + kb);
                bl[p * 2][0] = r0; bl[p * 2][1] = r1;
                bl[p * 2 + 1][0] = r2; bl[p * 2 + 1][1] = r3;
            }
#pragma unroll
            for (int mi = 0; mi < 2; mi++)
#pragma unroll
                for (int ni = 0; ni < 4; ni++)
                    mma16816_bf(acc[mi][ni], ah[mi], bh[ni][0], bh[ni][1]);
#pragma unroll
            for (int mi = 0; mi < 2; mi++)
#pragma unroll
                for (int ni = 0; ni < 4; ni++)
                    mma16816_bf(acc[mi][ni], ah[mi], bl[ni][0], bl[ni][1]);
#pragma unroll
            for (int mi = 0; mi < 2; mi++)
#pragma unroll
                for (int ni = 0; ni < 4; ni++)
                    mma16816_bf(acc[mi][ni], al[mi], bh[ni][0], bh[ni][1]);
        }

#pragma unroll
        for (int mi = 0; mi < 2; mi++) {
#pragma unroll
            for (int hh = 0; hh < 2; hh++) {
                int row = m0 + wm * 32 + mi * 16 + groupID + hh * 8;
                bool rok = row < M;
#pragma unroll
                for (int ni = 0; ni < 4; ni++) {
                    int col = n0 + wn * 32 + ni * 8 + tg * 2;
                    float v0 = acc[mi][ni][hh * 2]     + bias[col];
                    float v1 = acc[mi][ni][hh * 2 + 1] + bias[col + 1];
                    float2 hv = *(const float2*)&hold[(size_t)row * 128 + col];
                    v0 = g * v0 + og * hv.x;
                    v1 = g * v1 + og * hv.y;
                    if (!FC) {
                        if (rok) {
                            float2 o; o.x = v0; o.y = v1;
                            *(float2*)&Cq[(size_t)row * 128 + col] = o;
                        }
                    } else {
                        fc0[mi][hh] += v0 * Wfc[col * 2]     + v1 * Wfc[col * 2 + 2];
                        fc1[mi][hh] += v0 * Wfc[col * 2 + 1] + v1 * Wfc[col * 2 + 3];
                    }
                }
            }
        }
    }

    if (FC) {
        float* fcbuf = (float*)(smem + SM_FC);
#pragma unroll
        for (int mi = 0; mi < 2; mi++) {
#pragma unroll
            for (int hh = 0; hh < 2; hh++) {
                float a0 = fc0[mi][hh], a1 = fc1[mi][hh];
                a0 += __shfl_xor_sync(0xffffffffu, a0, 1);
                a0 += __shfl_xor_sync(0xffffffffu, a0, 2);
                a1 += __shfl_xor_sync(0xffffffffu, a1, 1);
                a1 += __shfl_xor_sync(0xffffffffu, a1, 2);
                int rowl = wm * 32 + mi * 16 + groupID + hh * 8;
                if (tg == 0) {
                    fcbuf[(wn * 128 + rowl) * 2]     = a0;
                    fcbuf[(wn * 128 + rowl) * 2 + 1] = a1;
                }
            }
        }
        __syncthreads();
        if (tid < 128) {
            int gr = m0 + tid;
            if (gr < M) {
                float o0 = fcbuf[tid * 2]     + fcbuf[(128 + tid) * 2]     + bfc[0];
                float o1 = fcbuf[tid * 2 + 1] + fcbuf[(128 + tid) * 2 + 1] + bfc[1];
                outp[(size_t)gr * 2]     = o0;
                outp[(size_t)gr * 2 + 1] = o1;
            }
        }
    }
}

// ---------------- edge phase: one warp per dst node, 4-edge batched -----------
__global__ void __launch_bounds__(256) k_edge(const float* __restrict__ prel) {
    int w = (blockIdx.x * blockDim.x + threadIdx.x) >> 5;
    int lane = threadIdx.x & 31;
    if (w >= NN) return;
    int r0 = g_rowstart[w], r1 = g_rowstart[w + 1];
    int h = lane >> 3;
    uint2 qb = __ldcs((const uint2*)&g_qh[(size_t)w * 128 + lane * 4]);
    __half2 qh0, qh1;
    memcpy(&qh0, &qb.x, 4); memcpy(&qh1, &qb.y, 4);
    float2 qf0 = __half22float2(qh0), qf1 = __half22float2(qh1);
    const float4 q4 = {qf0.x, qf0.y, qf1.x, qf1.y};
    const float scale = prel[h] * 0.17677669529663687f;
    float denom = 0.f;
    float4 acc = {0.f, 0.f, 0.f, 0.f};

    int j = r0;
    for (; j + 4 <= r1; j += 4) {
        int s[4];
#pragma unroll
        for (int u = 0; u < 4; u++) s[u] = __ldcs(&g_srcs[j + u]);
        uint2 kb[4], vb[4];
#pragma unroll
        for (int u = 0; u < 4; u++) {
            kb[u] = *(const uint2*)&g_kv[(size_t)s[u] * 256 + lane * 4];
            vb[u] = *(const uint2*)&g_kv[(size_t)s[u] * 256 + 128 + lane * 4];
        }
        float ev[4];
#pragma unroll
        for (int u = 0; u < 4; u++) {
            __half2 k0, k1;
            memcpy(&k0, &kb[u].x, 4); memcpy(&k1, &kb[u].y, 4);
            float2 kf0 = __half22float2(k0), kf1 = __half22float2(k1);
            float p = q4.x * kf0.x + q4.y * kf0.y + q4.z * kf1.x + q4.w * kf1.y;
            p += __shfl_xor_sync(0xffffffffu, p, 1);
            p += __shfl_xor_sync(0xffffffffu, p, 2);
            p += __shfl_xor_sync(0xffffffffu, p, 4);
            ev[u] = __expf(p * scale);
        }
#pragma unroll
        for (int u = 0; u < 4; u++) {
            __half2 v0, v1;
            memcpy(&v0, &vb[u].x, 4); memcpy(&v1, &vb[u].y, 4);
            float2 vf0 = __half22float2(v0), vf1 = __half22float2(v1);
            denom += ev[u];
            acc.x += ev[u] * vf0.x;
            acc.y += ev[u] * vf0.y;
            acc.z += ev[u] * vf1.x;
            acc.w += ev[u] * vf1.y;
        }
    }
    for (; j < r1; j++) {
        int s = __ldcs(&g_srcs[j]);
        uint2 kbits = *(const uint2*)&g_kv[(size_t)s * 256 + lane * 4];
        uint2 vbits = *(const uint2*)&g_kv[(size_t)s * 256 + 128 + lane * 4];
        __half2 k0, k1, v0, v1;
        memcpy(&k0, &kbits.x, 4); memcpy(&k1, &kbits.y, 4);
        memcpy(&v0, &vbits.x, 4); memcpy(&v1, &vbits.y, 4);
        float2 kf0 = __half22float2(k0), kf1 = __half22float2(k1);
        float p = q4.x * kf0.x + q4.y * kf0.y + q4.z * kf1.x + q4.w * kf1.y;
        p += __shfl_xor_sync(0xffffffffu, p, 1);
        p += __shfl_xor_sync(0xffffffffu, p, 2);
        p += __shfl_xor_sync(0xffffffffu, p, 4);
        float ev = __expf(p * scale);
        denom += ev;
        float2 vf0 = __half22float2(v0), vf1 = __half22float2(v1);
        acc.x += ev * vf0.x;
        acc.y += ev * vf0.y;
        acc.z += ev * vf1.x;
        acc.w += ev * vf1.y;
    }
    float inv = (r1 > r0) ? 1.f / denom : 0.f;
    acc.x *= inv; acc.y *= inv; acc.z *= inv; acc.w *= inv;
    __stcs((float4*)&g_agg[(size_t)w * CC + lane * 4], acc);
}

// -----------------------------------------------------------------------------
extern "C" void kernel_launch(void* const* d_in, const int* in_sizes, int n_in,
                              void* d_out, int out_size) {
    const float* x     = (const float*)d_in[0];
    const void*  ei    = d_in[1];
    const float* Wk    = (const float*)d_in[2];
    const float* bk    = (const float*)d_in[3];
    const float* Wq    = (const float*)d_in[4];
    const float* bq    = (const float*)d_in[5];
    const float* Wv    = (const float*)d_in[6];
    const float* bv    = (const float*)d_in[7];
    const float* a_rel = (const float*)d_in[8];
    const float* m_rel = (const float*)d_in[9];
    const float* p_rel = (const float*)d_in[10];
    const float* Wa    = (const float*)d_in[11];
    const float* ba    = (const float*)d_in[12];
    const float* skip  = (const float*)d_in[13];
    const float* Wfc   = (const float*)d_in[14];
    const float* bfc   = (const float*)d_in[15];
    float* out = (float*)d_out;

    int E = in_sizes[1] / 2;
    if (E > EE) E = EE;

    float *p_h, *p_agg, *p_b3;
    __half *p_qh, *p_kv, *p_w3h;
    __nv_bfloat16 *p_wabf;
    cudaGetSymbolAddress((void**)&p_h, g_h);
    cudaGetSymbolAddress((void**)&p_agg, g_agg);
    cudaGetSymbolAddress((void**)&p_qh, g_qh);
    cudaGetSymbolAddress((void**)&p_kv, g_kv);
    cudaGetSymbolAddress((void**)&p_b3, g_b3);
    cudaGetSymbolAddress((void**)&p_w3h, g_w3h);
    cudaGetSymbolAddress((void**)&p_wabf, g_wabf);

    cudaFuncSetAttribute(k_qkv, cudaFuncAttributeMaxDynamicSharedMemorySize, SMEM_QKV);
    cudaFuncSetAttribute(k_hmma<false>, cudaFuncAttributeMaxDynamicSharedMemorySize, SMEM_MMA);
    cudaFuncSetAttribute(k_hmma<true>,  cudaFuncAttributeMaxDynamicSharedMemorySize, SMEM_MMA);

    int eb2 = (E / 2 + 255) / 256;
    int eb = (E + 255) / 256;
    int nb1024 = (NN + 1023) / 1024;
    int mtiles = (NN + 127) / 128;          // 782
    int sgrid = (NN * 32 + 255) / 256;      // 12500

    k_zero<<<(NN + 255) / 256, 256>>>(ei, NN);                 // 1
    k_convert<<<eb2, 256>>>(ei, E);                            // 2
    k_fold<<<(CC * 384 + 255) / 256, 256>>>(Wq, Wk, Wv, bq, bk, bv, a_rel, m_rel, 0); // 3
    k_qkv<<<mtiles, 256, SMEM_QKV>>>(x, p_w3h, p_b3, p_qh, p_kv, NN);                 // 4
    k_wsplit<<<(128 * 128 + 255) / 256, 256>>>(Wa, p_wabf, 128);                      // 5
    k_scan1<<<nb1024, 1024>>>(NN);                             // 6
    k_scan2<<<1, 128>>>(nb1024);                               // 7
    k_scan3<<<(NN + 255) / 256, 256>>>(NN, E);                 // 8
    k_scatter<<<eb, 256>>>(E);                                 // 9

    k_edge<<<sgrid, 256>>>(p_rel);                             // 10
    k_hmma<false><<<mtiles, 256, SMEM_MMA>>>(                  // 11
        p_agg, p_wabf, ba, p_h, NN, x, skip, nullptr, nullptr, nullptr);

    k_fold<<<(CC * 384 + 255) / 256, 256>>>(Wq, Wk, Wv, bq, bk, bv, a_rel, m_rel, 1); // 12
    k_wsplit<<<(128 * 128 + 255) / 256, 256>>>(Wa + (size_t)CC * CC, p_wabf, 128);    // 13
    k_qkv<<<mtiles, 256, SMEM_QKV>>>(p_h, p_w3h, p_b3, p_qh, p_kv, NN);               // 14
    k_edge<<<sgrid, 256>>>(p_rel + HH);                        // 15
    k_hmma<true><<<mtiles, 256, SMEM_MMA>>>(                   // 16
        p_agg, p_wabf, ba + CC, nullptr, NN, p_h, skip + 1, Wfc, bfc, out);
}

// round 13
// speedup vs baseline: 1.3046x; 1.0145x over previous
#include <cuda_runtime.h>
#include <cuda_bf16.h>
#include <cuda_fp16.h>
#include <math.h>
#include <stdint.h>

#define NN 100000
#define CC 128
#define EE 1600000
#define HH 4
#define DD 32
#define LL 2

// ---------------- device scratch (allocation-free: static globals) ----------
__device__ int   g_is64;
__device__ int   g_src[EE];
__device__ int   g_dst[EE];
__device__ int   g_srcs[EE];
__device__ int   g_count[NN];
__device__ int   g_rowstart[NN + 2];
__device__ int   g_cursor[NN];
__device__ int   g_bsum[128];
__device__ int   g_bsum2[128];
__device__ __half g_qh[(size_t)NN * 128];      // Q fp16
__device__ __half g_kv[(size_t)NN * 256];      // [n][0:128]=K' fp16  [128:256]=V' fp16
__device__ float g_agg[(size_t)NN * CC];
__device__ float g_h[(size_t)NN * CC];
__device__ float g_b3[384];
__device__ __half g_w3h[384 * 128];            // W3^T fp16: [n][c]
__device__ __nv_bfloat16 g_wabf[128 * 256];    // Wa^T split: [n][0:128]=hi [128:256]=lo

// ---------------- zero + edge-index dtype detection (fused) ------------------
__global__ void k_zero(const void* ei, int n) {
    int i = blockIdx.x * blockDim.x + threadIdx.x;
    if (i < n) g_count[i] = 0;
    if (blockIdx.x == 0 && threadIdx.x == 0) {
        const long long* q = (const long long*)ei;
        int is64 = 1;
        for (int k = 0; k < 64; k++) {
            long long v = q[k];
            if (v < 0 || v >= NN) { is64 = 0; break; }
        }
        g_is64 = is64;
    }
}

// 2 edges per thread, 16B vector loads
__global__ void k_convert(const void* ei, int E) {
    int t = blockIdx.x * blockDim.x + threadIdx.x;
    int e = t * 2;
    if (e >= E) return;
    bool two = (e + 1 < E);
    int s0, d0, s1 = 0, d1 = 0;
    if (g_is64) {
        const longlong2* ps = (const longlong2*)ei;
        const longlong2* pd = (const longlong2*)((const long long*)ei + E);
        longlong2 sv = ps[t], dv = pd[t];
        s0 = (int)sv.x; s1 = (int)sv.y;
        d0 = (int)dv.x; d1 = (int)dv.y;
    } else {
        const int2* ps = (const int2*)ei;
        const int2* pd = (const int2*)((const int*)ei + E);
        int2 sv = ps[t], dv = pd[t];
        s0 = sv.x; s1 = sv.y;
        d0 = dv.x; d1 = dv.y;
    }
    g_src[e] = s0; g_dst[e] = d0;
    atomicAdd(&g_count[d0], 1);
    if (two) {
        g_src[e + 1] = s1; g_dst[e + 1] = d1;
        atomicAdd(&g_count[d1], 1);
    }
}

// ---------------- counting sort by dst ---------------------------------------
__global__ void k_scan1(int n) {
    __shared__ int sh[1024];
    int i = blockIdx.x * 1024 + threadIdx.x;
    int v = (i < n) ? g_count[i] : 0;
    sh[threadIdx.x] = v;
    __syncthreads();
    for (int off = 1; off < 1024; off <<= 1) {
        int t = (threadIdx.x >= off) ? sh[threadIdx.x - off] : 0;
        __syncthreads();
        sh[threadIdx.x] += t;
        __syncthreads();
    }
    if (i < n) g_rowstart[i] = sh[threadIdx.x] - v;
    if (threadIdx.x == 1023) g_bsum[blockIdx.x] = sh[1023];
}

__global__ void k_scan2(int nb) {
    __shared__ int sh[128];
    int v = (threadIdx.x < nb) ? g_bsum[threadIdx.x] : 0;
    sh[threadIdx.x] = v;
    __syncthreads();
    for (int off = 1; off < 128; off <<= 1) {
        int t = (threadIdx.x >= off) ? sh[threadIdx.x - off] : 0;
        __syncthreads();
        sh[threadIdx.x] += t;
        __syncthreads();
    }
    g_bsum2[threadIdx.x] = sh[threadIdx.x] - v;
}

__global__ void k_scan3(int n, int E) {
    int i = blockIdx.x * blockDim.x + threadIdx.x;
    if (i < n) {
        int r = g_rowstart[i] + g_bsum2[i >> 10];
        g_rowstart[i] = r;
        g_cursor[i] = r;
    }
    if (i == 0) g_rowstart[n] = E;
}

__global__ void k_scatter(int E) {
    int e = blockIdx.x * blockDim.x + threadIdx.x;
    if (e >= E) return;
    int d = g_dst[e];
    int pos = atomicAdd(&g_cursor[d], 1);
    g_srcs[pos] = g_src[e];
}

// ---------------- fold relation transforms -> transposed fp16 W3 -------------
__global__ void k_fold(const float* __restrict__ Wq, const float* __restrict__ Wk,
                       const float* __restrict__ Wv, const float* __restrict__ bq,
                       const float* __restrict__ bk, const float* __restrict__ bv,
                       const float* __restrict__ a_rel, const float* __restrict__ m_rel,
                       int l) {
    int idx = blockIdx.x * blockDim.x + threadIdx.x;
    if (idx >= CC * 384) return;
    int c = idx / 384, j = idx % 384;
    float val;
    if (j < 128) {
        val = Wq[((size_t)l * CC + c) * CC + j];
    } else {
        int e = (j < 256) ? j - 128 : j - 256;
        int h = e >> 5, ee = e & 31;
        const float* Wx = (j < 256) ? Wk : Wv;
        const float* Rx = (j < 256) ? a_rel : m_rel;
        const float* wrow = Wx + ((size_t)l * CC + c) * CC + h * DD;
        const float* rr = Rx + ((size_t)(l * HH + h) * DD) * DD + ee;
        float s = 0.f;
#pragma unroll
        for (int d = 0; d < DD; d++) s += wrow[d] * rr[d * DD];
        val = s;
    }
    g_w3h[(size_t)j * 128 + c] = __float2half_rn(val);
    if (c == 0) {
        float bval;
        if (j < 128) {
            bval = bq[l * CC + j];
        } else {
            int e = (j < 256) ? j - 128 : j - 256;
            int h = e >> 5, ee = e & 31;
            const float* bx = (j < 256) ? bk : bv;
            const float* Rx = (j < 256) ? a_rel : m_rel;
            float s = 0.f;
#pragma unroll
            for (int d = 0; d < DD; d++)
                s += bx[l * CC + h * DD + d] * Rx[((size_t)(l * HH + h) * DD + d) * DD + ee];
            bval = s;
        }
        g_b3[j] = bval;
    }
}

// ---------------- transpose + hi/lo bf16 split of Wa --------------------------
__global__ void k_wsplit(const float* __restrict__ W, __nv_bfloat16* __restrict__ dst,
                         int Ncols) {
    int idx = blockIdx.x * blockDim.x + threadIdx.x;
    if (idx >= 128 * Ncols) return;
    int n = idx >> 7, k = idx & 127;
    float v = W[(size_t)k * Ncols + n];
    __nv_bfloat16 hi = __float2bfloat16_rn(v);
    __nv_bfloat16 lo = __float2bfloat16_rn(v - __bfloat162float(hi));
    dst[(size_t)n * 256 + k] = hi;
    dst[(size_t)n * 256 + 128 + k] = lo;
}

// ================= shared GEMM helpers ========================================
#define LDT 136

__device__ __forceinline__ void ldsm_x4(uint32_t& r0, uint32_t& r1, uint32_t& r2,
                                        uint32_t& r3, uint32_t addr) {
    asm volatile("ldmatrix.sync.aligned.m8n8.x4.shared.b16 {%0,%1,%2,%3}, [%4];"
                 : "=r"(r0), "=r"(r1), "=r"(r2), "=r"(r3) : "r"(addr));
}

__device__ __forceinline__ void mma16816_bf(float* d, const uint32_t* a,
                                            uint32_t b0, uint32_t b1) {
    asm volatile(
        "mma.sync.aligned.m16n8k16.row.col.f32.bf16.bf16.f32 "
        "{%0,%1,%2,%3}, {%4,%5,%6,%7}, {%8,%9}, {%0,%1,%2,%3};"
        : "+f"(d[0]), "+f"(d[1]), "+f"(d[2]), "+f"(d[3])
        : "r"(a[0]), "r"(a[1]), "r"(a[2]), "r"(a[3]), "r"(b0), "r"(b1));
}

__device__ __forceinline__ void mma16816_f16(float* d, const uint32_t* a,
                                             uint32_t b0, uint32_t b1) {
    asm volatile(
        "mma.sync.aligned.m16n8k16.row.col.f32.f16.f16.f32 "
        "{%0,%1,%2,%3}, {%4,%5,%6,%7}, {%8,%9}, {%0,%1,%2,%3};"
        : "+f"(d[0]), "+f"(d[1]), "+f"(d[2]), "+f"(d[3])
        : "r"(a[0]), "r"(a[1]), "r"(a[2]), "r"(a[3]), "r"(b0), "r"(b1));
}

__device__ __forceinline__ uint32_t pack_bf2(float a, float b) {
    __nv_bfloat162 t = __halves2bfloat162(__float2bfloat16_rn(a), __float2bfloat16_rn(b));
    uint32_t r;
    memcpy(&r, &t, 4);
    return r;
}

#define CP_ASYNC16(dst_u32, src_ptr) \
    asm volatile("cp.async.cg.shared.global [%0], [%1], 16;" \
                 :: "r"(dst_u32), "l"(src_ptr))
#define CP_COMMIT() asm volatile("cp.async.commit_group;" ::: "memory")
#define CP_WAIT0()  asm volatile("cp.async.wait_group 0;" ::: "memory")

// ---------------- QKV GEMM: single-pass fp16, wide warp tile ------------------
// [Q|K'|V'] = A_fp32 @ W3_fp16, fp16 outputs. CTA tile 128(M) x 128(N), NB=3.
// Warp tile 32x64 (4m x 2n). Per k-step: 6 ldsm.x4 -> 16 MMAs (ratio 2.67).
// smem ~70KB -> 2 CTAs/SM.
#define QK_A (128 * LDT * 2)
#define QK_B (128 * LDT * 2)
#define SMEM_QKV (QK_A + QK_B)

__global__ void __launch_bounds__(256, 2) k_qkv(
    const float* __restrict__ A,
    const __half* __restrict__ W,      // [384][128] fp16, n-major
    const float* __restrict__ bias,
    __half* __restrict__ qh,
    __half* __restrict__ kvout,
    int M) {
    extern __shared__ __align__(16) char smem[];
    uint32_t smem_base;
    asm("{ .reg .u64 t; cvta.to.shared.u64 t, %1; cvt.u32.u64 %0, t; }"
        : "=r"(smem_base) : "l"(smem));

    int tid = threadIdx.x, wid = tid >> 5, lane = tid & 31;
    int wm = wid & 3, wn = wid >> 2;          // 4m x 2n
    int m0 = blockIdx.x * 128;

    // ---- A fp32 -> fp16 into smem (once)
#pragma unroll
    for (int it = 0; it < 16; it++) {
        int idx = it * 256 + tid;
        int r = idx >> 5, u = idx & 31;
        int gr = m0 + r;
        if (gr >= M) gr = M - 1;
        float4 v = *(const float4*)&A[(size_t)gr * 128 + u * 4];
        __half2 h0 = __floats2half2_rn(v.x, v.y);
        __half2 h1 = __floats2half2_rn(v.z, v.w);
        uint32_t b0, b1;
        memcpy(&b0, &h0, 4); memcpy(&b1, &h1, 4);
        *(uint2*)(smem + (uint32_t)(r * LDT + u * 4) * 2) = make_uint2(b0, b1);
    }

    uint32_t a_off[2], b_off[4];
#pragma unroll
    for (int mi = 0; mi < 2; mi++) {
        int arow = wm * 32 + mi * 16 + (lane & 7) + ((lane >> 3) & 1) * 8;
        int akc = (lane >> 4) * 8;
        a_off[mi] = (uint32_t)(arow * LDT + akc) * 2;
    }
#pragma unroll
    for (int p = 0; p < 4; p++) {
        int nrow = wn * 64 + p * 16 + (lane >> 4) * 8 + (lane & 7);
        int bkc = ((lane >> 3) & 1) * 8;
        b_off[p] = (uint32_t)(nrow * LDT + bkc) * 2;
    }
    int groupID = lane >> 2, tg = lane & 3;

    for (int bt = 0; bt < 3; bt++) {
        int n0 = bt * 128;
        __syncthreads();
        // ---- B subtile via cp.async: 128 rows x 256B
        {
            const char* Wb = (const char*)W;
#pragma unroll
            for (int it = 0; it < 8; it++) {
                int idx = it * 256 + tid;
                int r = idx >> 4, u = idx & 15;
                const char* src = Wb + (size_t)(n0 + r) * 256 + u * 16;
                uint32_t dst = smem_base + QK_A + (uint32_t)(r * LDT + u * 8) * 2;
                CP_ASYNC16(dst, src);
            }
            CP_COMMIT();
            CP_WAIT0();
        }
        __syncthreads();

        float acc[2][8][4];
#pragma unroll
        for (int mi = 0; mi < 2; mi++)
#pragma unroll
            for (int ni = 0; ni < 8; ni++)
#pragma unroll
                for (int c = 0; c < 4; c++) acc[mi][ni][c] = 0.f;

#pragma unroll
        for (int ks = 0; ks < 8; ks++) {
            uint32_t kb = (uint32_t)ks * 32;
            uint32_t a[2][4], b[8][2];
#pragma unroll
            for (int mi = 0; mi < 2; mi++)
                ldsm_x4(a[mi][0], a[mi][1], a[mi][2], a[mi][3],
                        smem_base + a_off[mi] + kb);
#pragma unroll
            for (int p = 0; p < 4; p++) {
                uint32_t r0, r1, r2, r3;
                ldsm_x4(r0, r1, r2, r3, smem_base + QK_A + b_off[p] + kb);
                b[p * 2][0] = r0; b[p * 2][1] = r1;
                b[p * 2 + 1][0] = r2; b[p * 2 + 1][1] = r3;
            }
#pragma unroll
            for (int mi = 0; mi < 2; mi++)
#pragma unroll
                for (int ni = 0; ni < 8; ni++)
                    mma16816_f16(acc[mi][ni], a[mi], b[ni][0], b[ni][1]);
        }

        // ---- epilogue: fp16 out
#pragma unroll
        for (int mi = 0; mi < 2; mi++) {
#pragma unroll
            for (int hh = 0; hh < 2; hh++) {
                int row = m0 + wm * 32 + mi * 16 + groupID + hh * 8;
                if (row >= M) continue;
#pragma unroll
                for (int ni = 0; ni < 8; ni++) {
                    int col = n0 + wn * 64 + ni * 8 + tg * 2;
                    float v0 = acc[mi][ni][hh * 2]     + bias[col];
                    float v1 = acc[mi][ni][hh * 2 + 1] + bias[col + 1];
                    __half2 hv2 = __floats2half2_rn(v0, v1);
                    uint32_t bits; memcpy(&bits, &hv2, 4);
                    if (bt == 0)
                        *(uint32_t*)&qh[(size_t)row * 128 + col] = bits;
                    else
                        *(uint32_t*)&kvout[(size_t)row * 256 + (col - 128)] = bits;
                }
            }
        }
    }
}

// ---------------- output GEMM: bf16 2-term split (R10 config) -----------------
// CTA tile 128(M) x 64(N), NB=2; smem 104KB -> 2 CTAs/SM; 8 ldsm -> 24 MMA/kstep.
#define A_TILE (128 * LDT * 2)
#define B_TILE (64 * LDT * 2)
#define SM_AH 0
#define SM_AL A_TILE
#define SM_BH (2 * A_TILE)
#define SM_BL (2 * A_TILE + B_TILE)
#define SM_FC (2 * A_TILE + 2 * B_TILE)
#define SMEM_MMA (SM_FC + 2048)

template <bool FC>
__global__ void __launch_bounds__(256, 2) k_hmma(
    const float* __restrict__ A,
    const __nv_bfloat16* __restrict__ Bbf,
    const float* __restrict__ bias,
    float* __restrict__ Cq,
    int M,
    const float* __restrict__ hold,
    const float* __restrict__ skipp,
    const float* __restrict__ Wfc,
    const float* __restrict__ bfc,
    float* __restrict__ outp) {
    extern __shared__ __align__(16) char smem[];
    uint32_t smem_base;
    asm("{ .reg .u64 t; cvta.to.shared.u64 t, %1; cvt.u32.u64 %0, t; }"
        : "=r"(smem_base) : "l"(smem));

    int tid = threadIdx.x, wid = tid >> 5, lane = tid & 31;
    int wm = wid & 3, wn = wid >> 2;
    int m0 = blockIdx.x * 128;

    // ---- load A fp32, GELU, split hi/lo into smem (once)
#pragma unroll
    for (int it = 0; it < 16; it++) {
        int idx = it * 256 + tid;
        int r = idx >> 5, u = idx & 31;
        int gr = m0 + r;
        if (gr >= M) gr = M - 1;
        float4 v = *(const float4*)&A[(size_t)gr * 128 + u * 4];
        v.x *= normcdff(v.x); v.y *= normcdff(v.y);
        v.z *= normcdff(v.z); v.w *= normcdff(v.w);
        uint32_t h01 = pack_bf2(v.x, v.y), h23 = pack_bf2(v.z, v.w);
        float rx = v.x - __bfloat162float(__float2bfloat16_rn(v.x));
        float ry = v.y - __bfloat162float(__float2bfloat16_rn(v.y));
        float rz = v.z - __bfloat162float(__float2bfloat16_rn(v.z));
        float rw = v.w - __bfloat162float(__float2bfloat16_rn(v.w));
        uint32_t l01 = pack_bf2(rx, ry), l23 = pack_bf2(rz, rw);
        uint32_t off = (uint32_t)(r * LDT + u * 4) * 2;
        *(uint2*)(smem + SM_AH + off) = make_uint2(h01, h23);
        *(uint2*)(smem + SM_AL + off) = make_uint2(l01, l23);
    }

    uint32_t a_off[2], b_off[2];
#pragma unroll
    for (int mi = 0; mi < 2; mi++) {
        int arow = wm * 32 + mi * 16 + (lane & 7) + ((lane >> 3) & 1) * 8;
        int akc = (lane >> 4) * 8;
        a_off[mi] = (uint32_t)(arow * LDT + akc) * 2;
    }
#pragma unroll
    for (int p = 0; p < 2; p++) {
        int nrow = wn * 32 + p * 16 + (lane >> 4) * 8 + (lane & 7);
        int bkc = ((lane >> 3) & 1) * 8;
        b_off[p] = (uint32_t)(nrow * LDT + bkc) * 2;
    }

    int groupID = lane >> 2, tg = lane & 3;
    float g = 1.f / (1.f + __expf(-skipp[0]));
    float og = 1.f - g;
    float fc0[2][2], fc1[2][2];
    if (FC) {
#pragma unroll
        for (int mi = 0; mi < 2; mi++)
#pragma unroll
            for (int hh = 0; hh < 2; hh++) { fc0[mi][hh] = 0.f; fc1[mi][hh] = 0.f; }
    }

    for (int bt = 0; bt < 2; bt++) {
        int n0 = bt * 64;
        __syncthreads();
        {
            const char* Bb = (const char*)Bbf;
#pragma unroll
            for (int it = 0; it < 8; it++) {
                int idx = it * 256 + tid;
                int r = idx >> 5, u = idx & 31;
                const char* src = Bb + (size_t)(n0 + r) * 512 + u * 16;
                uint32_t dst = smem_base + (u < 16 ? SM_BH : SM_BL)
                             + (uint32_t)(r * LDT + (u & 15) * 8) * 2;
                CP_ASYNC16(dst, src);
            }
            CP_COMMIT();
            CP_WAIT0();
        }
        __syncthreads();

        float acc[2][4][4];
#pragma unroll
        for (int mi = 0; mi < 2; mi++)
#pragma unroll
            for (int ni = 0; ni < 4; ni++)
#pragma unroll
                for (int c = 0; c < 4; c++) acc[mi][ni][c] = 0.f;

#pragma unroll
        for (int ks = 0; ks < 8; ks++) {
            uint32_t kb = (uint32_t)ks * 32;
            uint32_t ah[2][4], al[2][4], bh[4][2], bl[4][2];
#pragma unroll
            for (int mi = 0; mi < 2; mi++) {
                ldsm_x4(ah[mi][0], ah[mi][1], ah[mi][2], ah[mi][3],
                        smem_base + SM_AH + a_off[mi] + kb);
                ldsm_x4(al[mi][0], al[mi][1], al[mi][2], al[mi][3],
                        smem_base + SM_AL + a_off[mi] + kb);
            }
#pragma unroll
            for (int p = 0; p < 2; p++) {
                uint32_t r0, r1, r2, r3;
                ldsm_x4(r0, r1, r2, r3, smem_base + SM_BH + b_off[p] + kb);
                bh[p * 2][0] = r0; bh[p * 2][1] = r1;
                bh[p * 2 + 1][0] = r2; bh[p * 2 + 1][1] = r3;
                ldsm_x4(r0, r1, r2, r3, smem_base + SM_BL + b_off[p] + kb);
                bl[p * 2][0] = r0; bl[p * 2][1] = r1;
                bl[p * 2 + 1][0] = r2; bl[p * 2 + 1][1] = r3;
            }
#pragma unroll
            for (int mi = 0; mi < 2; mi++)
#pragma unroll
                for (int ni = 0; ni < 4; ni++)
                    mma16816_bf(acc[mi][ni], ah[mi], bh[ni][0], bh[ni][1]);
#pragma unroll
            for (int mi = 0; mi < 2; mi++)
#pragma unroll
                for (int ni = 0; ni < 4; ni++)
                    mma16816_bf(acc[mi][ni], ah[mi], bl[ni][0], bl[ni][1]);
#pragma unroll
            for (int mi = 0; mi < 2; mi++)
#pragma unroll
                for (int ni = 0; ni < 4; ni++)
                    mma16816_bf(acc[mi][ni], al[mi], bh[ni][0], bh[ni][1]);
        }

#pragma unroll
        for (int mi = 0; mi < 2; mi++) {
#pragma unroll
            for (int hh = 0; hh < 2; hh++) {
                int row = m0 + wm * 32 + mi * 16 + groupID + hh * 8;
                bool rok = row < M;
#pragma unroll
                for (int ni = 0; ni < 4; ni++) {
                    int col = n0 + wn * 32 + ni * 8 + tg * 2;
                    float v0 = acc[mi][ni][hh * 2]     + bias[col];
                    float v1 = acc[mi][ni][hh * 2 + 1] + bias[col + 1];
                    float2 hv = *(const float2*)&hold[(size_t)row * 128 + col];
                    v0 = g * v0 + og * hv.x;
                    v1 = g * v1 + og * hv.y;
                    if (!FC) {
                        if (rok) {
                            float2 o; o.x = v0; o.y = v1;
                            *(float2*)&Cq[(size_t)row * 128 + col] = o;
                        }
                    } else {
                        fc0[mi][hh] += v0 * Wfc[col * 2]     + v1 * Wfc[col * 2 + 2];
                        fc1[mi][hh] += v0 * Wfc[col * 2 + 1] + v1 * Wfc[col * 2 + 3];
                    }
                }
            }
        }
    }

    if (FC) {
        float* fcbuf = (float*)(smem + SM_FC);
#pragma unroll
        for (int mi = 0; mi < 2; mi++) {
#pragma unroll
            for (int hh = 0; hh < 2; hh++) {
                float a0 = fc0[mi][hh], a1 = fc1[mi][hh];
                a0 += __shfl_xor_sync(0xffffffffu, a0, 1);
                a0 += __shfl_xor_sync(0xffffffffu, a0, 2);
                a1 += __shfl_xor_sync(0xffffffffu, a1, 1);
                a1 += __shfl_xor_sync(0xffffffffu, a1, 2);
                int rowl = wm * 32 + mi * 16 + groupID + hh * 8;
                if (tg == 0) {
                    fcbuf[(wn * 128 + rowl) * 2]     = a0;
                    fcbuf[(wn * 128 + rowl) * 2 + 1] = a1;
                }
            }
        }
        __syncthreads();
        if (tid < 128) {
            int gr = m0 + tid;
            if (gr < M) {
                float o0 = fcbuf[tid * 2]     + fcbuf[(128 + tid) * 2]     + bfc[0];
                float o1 = fcbuf[tid * 2 + 1] + fcbuf[(128 + tid) * 2 + 1] + bfc[1];
                outp[(size_t)gr * 2]     = o0;
                outp[(size_t)gr * 2 + 1] = o1;
            }
        }
    }
}

// ---------------- edge phase: one warp per dst node, 4-edge batched -----------
__global__ void __launch_bounds__(256) k_edge(const float* __restrict__ prel) {
    int w = (blockIdx.x * blockDim.x + threadIdx.x) >> 5;
    int lane = threadIdx.x & 31;
    if (w >= NN) return;
    int r0 = g_rowstart[w], r1 = g_rowstart[w + 1];
    int h = lane >> 3;
    uint2 qb = __ldcs((const uint2*)&g_qh[(size_t)w * 128 + lane * 4]);
    __half2 qh0, qh1;
    memcpy(&qh0, &qb.x, 4); memcpy(&qh1, &qb.y, 4);
    float2 qf0 = __half22float2(qh0), qf1 = __half22float2(qh1);
    const float4 q4 = {qf0.x, qf0.y, qf1.x, qf1.y};
    const float scale = prel[h] * 0.17677669529663687f;
    float denom = 0.f;
    float4 acc = {0.f, 0.f, 0.f, 0.f};

    int j = r0;
    for (; j + 4 <= r1; j += 4) {
        int s[4];
#pragma unroll
        for (int u = 0; u < 4; u++) s[u] = __ldcs(&g_srcs[j + u]);
        uint2 kb[4], vb[4];
#pragma unroll
        for (int u = 0; u < 4; u++) {
            kb[u] = *(const uint2*)&g_kv[(size_t)s[u] * 256 + lane * 4];
            vb[u] = *(const uint2*)&g_kv[(size_t)s[u] * 256 + 128 + lane * 4];
        }
        float ev[4];
#pragma unroll
        for (int u = 0; u < 4; u++) {
            __half2 k0, k1;
            memcpy(&k0, &kb[u].x, 4); memcpy(&k1, &kb[u].y, 4);
            float2 kf0 = __half22float2(k0), kf1 = __half22float2(k1);
            float p = q4.x * kf0.x + q4.y * kf0.y + q4.z * kf1.x + q4.w * kf1.y;
            p += __shfl_xor_sync(0xffffffffu, p, 1);
            p += __shfl_xor_sync(0xffffffffu, p, 2);
            p += __shfl_xor_sync(0xffffffffu, p, 4);
            ev[u] = __expf(p * scale);
        }
#pragma unroll
        for (int u = 0; u < 4; u++) {
            __half2 v0, v1;
            memcpy(&v0, &vb[u].x, 4); memcpy(&v1, &vb[u].y, 4);
            float2 vf0 = __half22float2(v0), vf1 = __half22float2(v1);
            denom += ev[u];
            acc.x += ev[u] * vf0.x;
            acc.y += ev[u] * vf0.y;
            acc.z += ev[u] * vf1.x;
            acc.w += ev[u] * vf1.y;
        }
    }
    for (; j < r1; j++) {
        int s = __ldcs(&g_srcs[j]);
        uint2 kbits = *(const uint2*)&g_kv[(size_t)s * 256 + lane * 4];
        uint2 vbits = *(const uint2*)&g_kv[(size_t)s * 256 + 128 + lane * 4];
        __half2 k0, k1, v0, v1;
        memcpy(&k0, &kbits.x, 4); memcpy(&k1, &kbits.y, 4);
        memcpy(&v0, &vbits.x, 4); memcpy(&v1, &vbits.y, 4);
        float2 kf0 = __half22float2(k0), kf1 = __half22float2(k1);
        float p = q4.x * kf0.x + q4.y * kf0.y + q4.z * kf1.x + q4.w * kf1.y;
        p += __shfl_xor_sync(0xffffffffu, p, 1);
        p += __shfl_xor_sync(0xffffffffu, p, 2);
        p += __shfl_xor_sync(0xffffffffu, p, 4);
        float ev = __expf(p * scale);
        denom += ev;
        float2 vf0 = __half22float2(v0), vf1 = __half22float2(v1);
        acc.x += ev * vf0.x;
        acc.y += ev * vf0.y;
        acc.z += ev * vf1.x;
        acc.w += ev * vf1.y;
    }
    float inv = (r1 > r0) ? 1.f / denom : 0.f;
    acc.x *= inv; acc.y *= inv; acc.z *= inv; acc.w *= inv;
    __stcs((float4*)&g_agg[(size_t)w * CC + lane * 4], acc);
}

// -----------------------------------------------------------------------------
extern "C" void kernel_launch(void* const* d_in, const int* in_sizes, int n_in,
                              void* d_out, int out_size) {
    const float* x     = (const float*)d_in[0];
    const void*  ei    = d_in[1];
    const float* Wk    = (const float*)d_in[2];
    const float* bk    = (const float*)d_in[3];
    const float* Wq    = (const float*)d_in[4];
    const float* bq    = (const float*)d_in[5];
    const float* Wv    = (const float*)d_in[6];
    const float* bv    = (const float*)d_in[7];
    const float* a_rel = (const float*)d_in[8];
    const float* m_rel = (const float*)d_in[9];
    const float* p_rel = (const float*)d_in[10];
    const float* Wa    = (const float*)d_in[11];
    const float* ba    = (const float*)d_in[12];
    const float* skip  = (const float*)d_in[13];
    const float* Wfc   = (const float*)d_in[14];
    const float* bfc   = (const float*)d_in[15];
    float* out = (float*)d_out;

    int E = in_sizes[1] / 2;
    if (E > EE) E = EE;

    float *p_h, *p_agg, *p_b3;
    __half *p_qh, *p_kv, *p_w3h;
    __nv_bfloat16 *p_wabf;
    cudaGetSymbolAddress((void**)&p_h, g_h);
    cudaGetSymbolAddress((void**)&p_agg, g_agg);
    cudaGetSymbolAddress((void**)&p_qh, g_qh);
    cudaGetSymbolAddress((void**)&p_kv, g_kv);
    cudaGetSymbolAddress((void**)&p_b3, g_b3);
    cudaGetSymbolAddress((void**)&p_w3h, g_w3h);
    cudaGetSymbolAddress((void**)&p_wabf, g_wabf);

    cudaFuncSetAttribute(k_qkv, cudaFuncAttributeMaxDynamicSharedMemorySize, SMEM_QKV);
    cudaFuncSetAttribute(k_hmma<false>, cudaFuncAttributeMaxDynamicSharedMemorySize, SMEM_MMA);
    cudaFuncSetAttribute(k_hmma<true>,  cudaFuncAttributeMaxDynamicSharedMemorySize, SMEM_MMA);

    int eb2 = (E / 2 + 255) / 256;
    int eb = (E + 255) / 256;
    int nb1024 = (NN + 1023) / 1024;
    int mtiles = (NN + 127) / 128;          // 782
    int sgrid = (NN * 32 + 255) / 256;      // 12500

    k_zero<<<(NN + 255) / 256, 256>>>(ei, NN);                 // 1
    k_convert<<<eb2, 256>>>(ei, E);                            // 2
    k_fold<<<(CC * 384 + 255) / 256, 256>>>(Wq, Wk, Wv, bq, bk, bv, a_rel, m_rel, 0); // 3
    k_qkv<<<mtiles, 256, SMEM_QKV>>>(x, p_w3h, p_b3, p_qh, p_kv, NN);                 // 4
    k_wsplit<<<(128 * 128 + 255) / 256, 256>>>(Wa, p_wabf, 128);                      // 5
    k_scan1<<<nb1024, 1024>>>(NN);                             // 6
    k_scan2<<<1, 128>>>(nb1024);                               // 7
    k_scan3<<<(NN + 255) / 256, 256>>>(NN, E);                 // 8
    k_scatter<<<eb, 256>>>(E);                                 // 9

    k_edge<<<sgrid, 256>>>(p_rel);                             // 10
    k_hmma<false><<<mtiles, 256, SMEM_MMA>>>(                  // 11
        p_agg, p_wabf, ba, p_h, NN, x, skip, nullptr, nullptr, nullptr);

    k_fold<<<(CC * 384 + 255) / 256, 256>>>(Wq, Wk, Wv, bq, bk, bv, a_rel, m_rel, 1); // 12
    k_wsplit<<<(128 * 128 + 255) / 256, 256>>>(Wa + (size_t)CC * CC, p_wabf, 128);    // 13
    k_qkv<<<mtiles, 256, SMEM_QKV>>>(p_h, p_w3h, p_b3, p_qh, p_kv, NN);               // 14
    k_edge<<<sgrid, 256>>>(p_rel + HH);                        // 15
    k_hmma<true><<<mtiles, 256, SMEM_MMA>>>(                   // 16
        p_agg, p_wabf, ba + CC, nullptr, NN, p_h, skip + 1, Wfc, bfc, out);
}

// round 14
// speedup vs baseline: 1.4389x; 1.1030x over previous
#include <cuda_runtime.h>
#include <cuda_bf16.h>
#include <cuda_fp16.h>
#include <math.h>
#include <stdint.h>

#define NN 100000
#define CC 128
#define EE 1600000
#define HH 4
#define DD 32
#define LL 2

// ---------------- device scratch (allocation-free: static globals) ----------
__device__ int   g_is64;
__device__ int   g_src[EE];
__device__ int   g_dst[EE];
__device__ int   g_srcs[EE];
__device__ int   g_count[NN];
__device__ int   g_rowstart[NN + 2];
__device__ int   g_cursor[NN];
__device__ int   g_bsum[128];
__device__ int   g_bsum2[128];
__device__ __half g_qh[(size_t)NN * 128];      // Q fp16
__device__ __half g_kv[(size_t)NN * 256];      // [n][0:128]=K' fp16  [128:256]=V' fp16
__device__ __half g_agg[(size_t)NN * CC];      // attention aggregate, fp16
__device__ float g_h[(size_t)NN * CC];
__device__ float g_b3[384];
__device__ __half g_w3h[384 * 128];            // W3^T fp16: [n][c]
__device__ __half g_wah[128 * 128];            // Wa^T fp16: [n][c]

// ---------------- zero + edge-index dtype detection (fused) ------------------
__global__ void k_zero(const void* ei, int n) {
    int i = blockIdx.x * blockDim.x + threadIdx.x;
    if (i < n) g_count[i] = 0;
    if (blockIdx.x == 0 && threadIdx.x == 0) {
        const long long* q = (const long long*)ei;
        int is64 = 1;
        for (int k = 0; k < 64; k++) {
            long long v = q[k];
            if (v < 0 || v >= NN) { is64 = 0; break; }
        }
        g_is64 = is64;
    }
}

// 2 edges per thread, 16B vector loads
__global__ void k_convert(const void* ei, int E) {
    int t = blockIdx.x * blockDim.x + threadIdx.x;
    int e = t * 2;
    if (e >= E) return;
    bool two = (e + 1 < E);
    int s0, d0, s1 = 0, d1 = 0;
    if (g_is64) {
        const longlong2* ps = (const longlong2*)ei;
        const longlong2* pd = (const longlong2*)((const long long*)ei + E);
        longlong2 sv = ps[t], dv = pd[t];
        s0 = (int)sv.x; s1 = (int)sv.y;
        d0 = (int)dv.x; d1 = (int)dv.y;
    } else {
        const int2* ps = (const int2*)ei;
        const int2* pd = (const int2*)((const int*)ei + E);
        int2 sv = ps[t], dv = pd[t];
        s0 = sv.x; s1 = sv.y;
        d0 = dv.x; d1 = dv.y;
    }
    g_src[e] = s0; g_dst[e] = d0;
    atomicAdd(&g_count[d0], 1);
    if (two) {
        g_src[e + 1] = s1; g_dst[e + 1] = d1;
        atomicAdd(&g_count[d1], 1);
    }
}

// ---------------- counting sort by dst ---------------------------------------
__global__ void k_scan1(int n) {
    __shared__ int sh[1024];
    int i = blockIdx.x * 1024 + threadIdx.x;
    int v = (i < n) ? g_count[i] : 0;
    sh[threadIdx.x] = v;
    __syncthreads();
    for (int off = 1; off < 1024; off <<= 1) {
        int t = (threadIdx.x >= off) ? sh[threadIdx.x - off] : 0;
        __syncthreads();
        sh[threadIdx.x] += t;
        __syncthreads();
    }
    if (i < n) g_rowstart[i] = sh[threadIdx.x] - v;
    if (threadIdx.x == 1023) g_bsum[blockIdx.x] = sh[1023];
}

__global__ void k_scan2(int nb) {
    __shared__ int sh[128];
    int v = (threadIdx.x < nb) ? g_bsum[threadIdx.x] : 0;
    sh[threadIdx.x] = v;
    __syncthreads();
    for (int off = 1; off < 128; off <<= 1) {
        int t = (threadIdx.x >= off) ? sh[threadIdx.x - off] : 0;
        __syncthreads();
        sh[threadIdx.x] += t;
        __syncthreads();
    }
    g_bsum2[threadIdx.x] = sh[threadIdx.x] - v;
}

__global__ void k_scan3(int n, int E) {
    int i = blockIdx.x * blockDim.x + threadIdx.x;
    if (i < n) {
        int r = g_rowstart[i] + g_bsum2[i >> 10];
        g_rowstart[i] = r;
        g_cursor[i] = r;
    }
    if (i == 0) g_rowstart[n] = E;
}

__global__ void k_scatter(int E) {
    int e = blockIdx.x * blockDim.x + threadIdx.x;
    if (e >= E) return;
    int d = g_dst[e];
    int pos = atomicAdd(&g_cursor[d], 1);
    g_srcs[pos] = g_src[e];
}

// ---------------- fold relation transforms -> transposed fp16 W3 -------------
__global__ void k_fold(const float* __restrict__ Wq, const float* __restrict__ Wk,
                       const float* __restrict__ Wv, const float* __restrict__ bq,
                       const float* __restrict__ bk, const float* __restrict__ bv,
                       const float* __restrict__ a_rel, const float* __restrict__ m_rel,
                       int l) {
    int idx = blockIdx.x * blockDim.x + threadIdx.x;
    if (idx >= CC * 384) return;
    int c = idx / 384, j = idx % 384;
    float val;
    if (j < 128) {
        val = Wq[((size_t)l * CC + c) * CC + j];
    } else {
        int e = (j < 256) ? j - 128 : j - 256;
        int h = e >> 5, ee = e & 31;
        const float* Wx = (j < 256) ? Wk : Wv;
        const float* Rx = (j < 256) ? a_rel : m_rel;
        const float* wrow = Wx + ((size_t)l * CC + c) * CC + h * DD;
        const float* rr = Rx + ((size_t)(l * HH + h) * DD) * DD + ee;
        float s = 0.f;
#pragma unroll
        for (int d = 0; d < DD; d++) s += wrow[d] * rr[d * DD];
        val = s;
    }
    g_w3h[(size_t)j * 128 + c] = __float2half_rn(val);
    if (c == 0) {
        float bval;
        if (j < 128) {
            bval = bq[l * CC + j];
        } else {
            int e = (j < 256) ? j - 128 : j - 256;
            int h = e >> 5, ee = e & 31;
            const float* bx = (j < 256) ? bk : bv;
            const float* Rx = (j < 256) ? a_rel : m_rel;
            float s = 0.f;
#pragma unroll
            for (int d = 0; d < DD; d++)
                s += bx[l * CC + h * DD + d] * Rx[((size_t)(l * HH + h) * DD + d) * DD + ee];
            bval = s;
        }
        g_b3[j] = bval;
    }
}

// ---------------- transpose Wa -> fp16 ----------------------------------------
__global__ void k_wh(const float* __restrict__ W, __half* __restrict__ dst) {
    int idx = blockIdx.x * blockDim.x + threadIdx.x;
    if (idx >= 128 * 128) return;
    int n = idx >> 7, k = idx & 127;
    dst[(size_t)n * 128 + k] = __float2half_rn(W[(size_t)k * 128 + n]);
}

// ================= shared GEMM helpers ========================================
#define LDT 136

__device__ __forceinline__ void ldsm_x4(uint32_t& r0, uint32_t& r1, uint32_t& r2,
                                        uint32_t& r3, uint32_t addr) {
    asm volatile("ldmatrix.sync.aligned.m8n8.x4.shared.b16 {%0,%1,%2,%3}, [%4];"
                 : "=r"(r0), "=r"(r1), "=r"(r2), "=r"(r3) : "r"(addr));
}

__device__ __forceinline__ void mma16816_f16(float* d, const uint32_t* a,
                                             uint32_t b0, uint32_t b1) {
    asm volatile(
        "mma.sync.aligned.m16n8k16.row.col.f32.f16.f16.f32 "
        "{%0,%1,%2,%3}, {%4,%5,%6,%7}, {%8,%9}, {%0,%1,%2,%3};"
        : "+f"(d[0]), "+f"(d[1]), "+f"(d[2]), "+f"(d[3])
        : "r"(a[0]), "r"(a[1]), "r"(a[2]), "r"(a[3]), "r"(b0), "r"(b1));
}

#define CP_ASYNC16(dst_u32, src_ptr) \
    asm volatile("cp.async.cg.shared.global [%0], [%1], 16;" \
                 :: "r"(dst_u32), "l"(src_ptr))
#define CP_COMMIT() asm volatile("cp.async.commit_group;" ::: "memory")
#define CP_WAIT0()  asm volatile("cp.async.wait_group 0;" ::: "memory")

// ---------------- QKV GEMM: single-pass fp16, wide warp tile ------------------
// [Q|K'|V'] = A_fp32 @ W3_fp16, fp16 outputs. CTA tile 128(M) x 128(N), NB=3.
// Warp tile 32x64 (4m x 2n). Per k-step: 6 ldsm.x4 -> 16 MMAs. 2 CTAs/SM.
#define QK_A (128 * LDT * 2)
#define QK_B (128 * LDT * 2)
#define SMEM_QKV (QK_A + QK_B)

__global__ void __launch_bounds__(256, 2) k_qkv(
    const float* __restrict__ A,
    const __half* __restrict__ W,      // [384][128] fp16, n-major
    const float* __restrict__ bias,
    __half* __restrict__ qh,
    __half* __restrict__ kvout,
    int M) {
    extern __shared__ __align__(16) char smem[];
    uint32_t smem_base;
    asm("{ .reg .u64 t; cvta.to.shared.u64 t, %1; cvt.u32.u64 %0, t; }"
        : "=r"(smem_base) : "l"(smem));

    int tid = threadIdx.x, wid = tid >> 5, lane = tid & 31;
    int wm = wid & 3, wn = wid >> 2;
    int m0 = blockIdx.x * 128;

    // ---- A fp32 -> fp16 into smem (once)
#pragma unroll
    for (int it = 0; it < 16; it++) {
        int idx = it * 256 + tid;
        int r = idx >> 5, u = idx & 31;
        int gr = m0 + r;
        if (gr >= M) gr = M - 1;
        float4 v = *(const float4*)&A[(size_t)gr * 128 + u * 4];
        __half2 h0 = __floats2half2_rn(v.x, v.y);
        __half2 h1 = __floats2half2_rn(v.z, v.w);
        uint32_t b0, b1;
        memcpy(&b0, &h0, 4); memcpy(&b1, &h1, 4);
        *(uint2*)(smem + (uint32_t)(r * LDT + u * 4) * 2) = make_uint2(b0, b1);
    }

    uint32_t a_off[2], b_off[4];
#pragma unroll
    for (int mi = 0; mi < 2; mi++) {
        int arow = wm * 32 + mi * 16 + (lane & 7) + ((lane >> 3) & 1) * 8;
        int akc = (lane >> 4) * 8;
        a_off[mi] = (uint32_t)(arow * LDT + akc) * 2;
    }
#pragma unroll
    for (int p = 0; p < 4; p++) {
        int nrow = wn * 64 + p * 16 + (lane >> 4) * 8 + (lane & 7);
        int bkc = ((lane >> 3) & 1) * 8;
        b_off[p] = (uint32_t)(nrow * LDT + bkc) * 2;
    }
    int groupID = lane >> 2, tg = lane & 3;

    for (int bt = 0; bt < 3; bt++) {
        int n0 = bt * 128;
        __syncthreads();
        {
            const char* Wb = (const char*)W;
#pragma unroll
            for (int it = 0; it < 8; it++) {
                int idx = it * 256 + tid;
                int r = idx >> 4, u = idx & 15;
                const char* src = Wb + (size_t)(n0 + r) * 256 + u * 16;
                uint32_t dst = smem_base + QK_A + (uint32_t)(r * LDT + u * 8) * 2;
                CP_ASYNC16(dst, src);
            }
            CP_COMMIT();
            CP_WAIT0();
        }
        __syncthreads();

        float acc[2][8][4];
#pragma unroll
        for (int mi = 0; mi < 2; mi++)
#pragma unroll
            for (int ni = 0; ni < 8; ni++)
#pragma unroll
                for (int c = 0; c < 4; c++) acc[mi][ni][c] = 0.f;

#pragma unroll
        for (int ks = 0; ks < 8; ks++) {
            uint32_t kb = (uint32_t)ks * 32;
            uint32_t a[2][4], b[8][2];
#pragma unroll
            for (int mi = 0; mi < 2; mi++)
                ldsm_x4(a[mi][0], a[mi][1], a[mi][2], a[mi][3],
                        smem_base + a_off[mi] + kb);
#pragma unroll
            for (int p = 0; p < 4; p++) {
                uint32_t r0, r1, r2, r3;
                ldsm_x4(r0, r1, r2, r3, smem_base + QK_A + b_off[p] + kb);
                b[p * 2][0] = r0; b[p * 2][1] = r1;
                b[p * 2 + 1][0] = r2; b[p * 2 + 1][1] = r3;
            }
#pragma unroll
            for (int mi = 0; mi < 2; mi++)
#pragma unroll
                for (int ni = 0; ni < 8; ni++)
                    mma16816_f16(acc[mi][ni], a[mi], b[ni][0], b[ni][1]);
        }

#pragma unroll
        for (int mi = 0; mi < 2; mi++) {
#pragma unroll
            for (int hh = 0; hh < 2; hh++) {
                int row = m0 + wm * 32 + mi * 16 + groupID + hh * 8;
                if (row >= M) continue;
#pragma unroll
                for (int ni = 0; ni < 8; ni++) {
                    int col = n0 + wn * 64 + ni * 8 + tg * 2;
                    float v0 = acc[mi][ni][hh * 2]     + bias[col];
                    float v1 = acc[mi][ni][hh * 2 + 1] + bias[col + 1];
                    __half2 hv2 = __floats2half2_rn(v0, v1);
                    uint32_t bits; memcpy(&bits, &hv2, 4);
                    if (bt == 0)
                        *(uint32_t*)&qh[(size_t)row * 128 + col] = bits;
                    else
                        *(uint32_t*)&kvout[(size_t)row * 256 + (col - 128)] = bits;
                }
            }
        }
    }
}

// ---------------- output GEMM: single-pass fp16 + GELU + blend (+FC) ----------
// out = gelu(agg_fp16) @ Wa_fp16 + ba; h = g*out + (1-g)*hold. CTA 128x128, NB=1.
#define SM_OFC (QK_A + QK_B)
#define SMEM_OUT (SM_OFC + 2048)

template <bool FC>
__global__ void __launch_bounds__(256, 2) k_out(
    const __half* __restrict__ Aagg,   // [M][128] fp16
    const __half* __restrict__ W,      // [128][128] fp16, n-major
    const float* __restrict__ bias,
    float* __restrict__ Ch,
    int M,
    const float* __restrict__ hold,
    const float* __restrict__ skipp,
    const float* __restrict__ Wfc,
    const float* __restrict__ bfc,
    float* __restrict__ outp) {
    extern __shared__ __align__(16) char smem[];
    uint32_t smem_base;
    asm("{ .reg .u64 t; cvta.to.shared.u64 t, %1; cvt.u32.u64 %0, t; }"
        : "=r"(smem_base) : "l"(smem));

    int tid = threadIdx.x, wid = tid >> 5, lane = tid & 31;
    int wm = wid & 3, wn = wid >> 2;
    int m0 = blockIdx.x * 128;

    // ---- agg fp16 -> GELU -> fp16 into smem; B tile via cp.async in parallel
    {
        const char* Wb = (const char*)W;
#pragma unroll
        for (int it = 0; it < 8; it++) {
            int idx = it * 256 + tid;
            int r = idx >> 4, u = idx & 15;
            const char* src = Wb + (size_t)r * 256 + u * 16;
            uint32_t dst = smem_base + QK_A + (uint32_t)(r * LDT + u * 8) * 2;
            CP_ASYNC16(dst, src);
        }
        CP_COMMIT();
    }
#pragma unroll
    for (int it = 0; it < 8; it++) {
        int idx = it * 256 + tid;
        int r = idx >> 4, u = idx & 15;      // u: 8-half (16B) units
        int gr = m0 + r;
        if (gr >= M) gr = M - 1;
        uint2 bits = *(const uint2*)&Aagg[(size_t)gr * 128 + u * 8];
        uint2 bits2 = *(const uint2*)&Aagg[(size_t)gr * 128 + u * 8 + 4];
        __half2 p0, p1, p2, p3;
        memcpy(&p0, &bits.x, 4); memcpy(&p1, &bits.y, 4);
        memcpy(&p2, &bits2.x, 4); memcpy(&p3, &bits2.y, 4);
        float2 f0 = __half22float2(p0), f1 = __half22float2(p1);
        float2 f2 = __half22float2(p2), f3 = __half22float2(p3);
        f0.x *= normcdff(f0.x); f0.y *= normcdff(f0.y);
        f1.x *= normcdff(f1.x); f1.y *= normcdff(f1.y);
        f2.x *= normcdff(f2.x); f2.y *= normcdff(f2.y);
        f3.x *= normcdff(f3.x); f3.y *= normcdff(f3.y);
        __half2 o0 = __floats2half2_rn(f0.x, f0.y);
        __half2 o1 = __floats2half2_rn(f1.x, f1.y);
        __half2 o2 = __floats2half2_rn(f2.x, f2.y);
        __half2 o3 = __floats2half2_rn(f3.x, f3.y);
        uint4 ob;
        memcpy(&ob.x, &o0, 4); memcpy(&ob.y, &o1, 4);
        memcpy(&ob.z, &o2, 4); memcpy(&ob.w, &o3, 4);
        *(uint4*)(smem + (uint32_t)(r * LDT + u * 8) * 2) = ob;
    }
    CP_WAIT0();
    __syncthreads();

    uint32_t a_off[2], b_off[4];
#pragma unroll
    for (int mi = 0; mi < 2; mi++) {
        int arow = wm * 32 + mi * 16 + (lane & 7) + ((lane >> 3) & 1) * 8;
        int akc = (lane >> 4) * 8;
        a_off[mi] = (uint32_t)(arow * LDT + akc) * 2;
    }
#pragma unroll
    for (int p = 0; p < 4; p++) {
        int nrow = wn * 64 + p * 16 + (lane >> 4) * 8 + (lane & 7);
        int bkc = ((lane >> 3) & 1) * 8;
        b_off[p] = (uint32_t)(nrow * LDT + bkc) * 2;
    }
    int groupID = lane >> 2, tg = lane & 3;
    float g = 1.f / (1.f + __expf(-skipp[0]));
    float og = 1.f - g;

    float acc[2][8][4];
#pragma unroll
    for (int mi = 0; mi < 2; mi++)
#pragma unroll
        for (int ni = 0; ni < 8; ni++)
#pragma unroll
            for (int c = 0; c < 4; c++) acc[mi][ni][c] = 0.f;

#pragma unroll
    for (int ks = 0; ks < 8; ks++) {
        uint32_t kb = (uint32_t)ks * 32;
        uint32_t a[2][4], b[8][2];
#pragma unroll
        for (int mi = 0; mi < 2; mi++)
            ldsm_x4(a[mi][0], a[mi][1], a[mi][2], a[mi][3],
                    smem_base + a_off[mi] + kb);
#pragma unroll
        for (int p = 0; p < 4; p++) {
            uint32_t r0, r1, r2, r3;
            ldsm_x4(r0, r1, r2, r3, smem_base + QK_A + b_off[p] + kb);
            b[p * 2][0] = r0; b[p * 2][1] = r1;
            b[p * 2 + 1][0] = r2; b[p * 2 + 1][1] = r3;
        }
#pragma unroll
        for (int mi = 0; mi < 2; mi++)
#pragma unroll
            for (int ni = 0; ni < 8; ni++)
                mma16816_f16(acc[mi][ni], a[mi], b[ni][0], b[ni][1]);
    }

    float fc0[2][2], fc1[2][2];
    if (FC) {
#pragma unroll
        for (int mi = 0; mi < 2; mi++)
#pragma unroll
            for (int hh = 0; hh < 2; hh++) { fc0[mi][hh] = 0.f; fc1[mi][hh] = 0.f; }
    }

#pragma unroll
    for (int mi = 0; mi < 2; mi++) {
#pragma unroll
        for (int hh = 0; hh < 2; hh++) {
            int row = m0 + wm * 32 + mi * 16 + groupID + hh * 8;
            bool rok = row < M;
#pragma unroll
            for (int ni = 0; ni < 8; ni++) {
                int col = wn * 64 + ni * 8 + tg * 2;
                float v0 = acc[mi][ni][hh * 2]     + bias[col];
                float v1 = acc[mi][ni][hh * 2 + 1] + bias[col + 1];
                float2 hv = *(const float2*)&hold[(size_t)row * 128 + col];
                v0 = g * v0 + og * hv.x;
                v1 = g * v1 + og * hv.y;
                if (!FC) {
                    if (rok) {
                        float2 o; o.x = v0; o.y = v1;
                        *(float2*)&Ch[(size_t)row * 128 + col] = o;
                    }
                } else {
                    fc0[mi][hh] += v0 * Wfc[col * 2]     + v1 * Wfc[col * 2 + 2];
                    fc1[mi][hh] += v0 * Wfc[col * 2 + 1] + v1 * Wfc[col * 2 + 3];
                }
            }
        }
    }

    if (FC) {
        float* fcbuf = (float*)(smem + SM_OFC);   // [2 wn][128 row][2]
#pragma unroll
        for (int mi = 0; mi < 2; mi++) {
#pragma unroll
            for (int hh = 0; hh < 2; hh++) {
                float a0 = fc0[mi][hh], a1 = fc1[mi][hh];
                a0 += __shfl_xor_sync(0xffffffffu, a0, 1);
                a0 += __shfl_xor_sync(0xffffffffu, a0, 2);
                a1 += __shfl_xor_sync(0xffffffffu, a1, 1);
                a1 += __shfl_xor_sync(0xffffffffu, a1, 2);
                int rowl = wm * 32 + mi * 16 + groupID + hh * 8;
                if (tg == 0) {
                    fcbuf[(wn * 128 + rowl) * 2]     = a0;
                    fcbuf[(wn * 128 + rowl) * 2 + 1] = a1;
                }
            }
        }
        __syncthreads();
        if (tid < 128) {
            int gr = m0 + tid;
            if (gr < M) {
                float o0 = fcbuf[tid * 2]     + fcbuf[(128 + tid) * 2]     + bfc[0];
                float o1 = fcbuf[tid * 2 + 1] + fcbuf[(128 + tid) * 2 + 1] + bfc[1];
                outp[(size_t)gr * 2]     = o0;
                outp[(size_t)gr * 2 + 1] = o1;
            }
        }
    }
}

// ---------------- edge phase: one warp per dst node, 4-edge batched -----------
__global__ void __launch_bounds__(256) k_edge(const float* __restrict__ prel) {
    int w = (blockIdx.x * blockDim.x + threadIdx.x) >> 5;
    int lane = threadIdx.x & 31;
    if (w >= NN) return;
    int r0 = g_rowstart[w], r1 = g_rowstart[w + 1];
    int h = lane >> 3;
    uint2 qb = __ldcs((const uint2*)&g_qh[(size_t)w * 128 + lane * 4]);
    __half2 qh0, qh1;
    memcpy(&qh0, &qb.x, 4); memcpy(&qh1, &qb.y, 4);
    float2 qf0 = __half22float2(qh0), qf1 = __half22float2(qh1);
    const float4 q4 = {qf0.x, qf0.y, qf1.x, qf1.y};
    const float scale = prel[h] * 0.17677669529663687f;
    float denom = 0.f;
    float4 acc = {0.f, 0.f, 0.f, 0.f};

    int j = r0;
    for (; j + 4 <= r1; j += 4) {
        int s[4];
#pragma unroll
        for (int u = 0; u < 4; u++) s[u] = __ldcs(&g_srcs[j + u]);
        uint2 kb[4], vb[4];
#pragma unroll
        for (int u = 0; u < 4; u++) {
            kb[u] = *(const uint2*)&g_kv[(size_t)s[u] * 256 + lane * 4];
            vb[u] = *(const uint2*)&g_kv[(size_t)s[u] * 256 + 128 + lane * 4];
        }
        float ev[4];
#pragma unroll
        for (int u = 0; u < 4; u++) {
            __half2 k0, k1;
            memcpy(&k0, &kb[u].x, 4); memcpy(&k1, &kb[u].y, 4);
            float2 kf0 = __half22float2(k0), kf1 = __half22float2(k1);
            float p = q4.x * kf0.x + q4.y * kf0.y + q4.z * kf1.x + q4.w * kf1.y;
            p += __shfl_xor_sync(0xffffffffu, p, 1);
            p += __shfl_xor_sync(0xffffffffu, p, 2);
            p += __shfl_xor_sync(0xffffffffu, p, 4);
            ev[u] = __expf(p * scale);
        }
#pragma unroll
        for (int u = 0; u < 4; u++) {
            __half2 v0, v1;
            memcpy(&v0, &vb[u].x, 4); memcpy(&v1, &vb[u].y, 4);
            float2 vf0 = __half22float2(v0), vf1 = __half22float2(v1);
            denom += ev[u];
            acc.x += ev[u] * vf0.x;
            acc.y += ev[u] * vf0.y;
            acc.z += ev[u] * vf1.x;
            acc.w += ev[u] * vf1.y;
        }
    }
    for (; j < r1; j++) {
        int s = __ldcs(&g_srcs[j]);
        uint2 kbits = *(const uint2*)&g_kv[(size_t)s * 256 + lane * 4];
        uint2 vbits = *(const uint2*)&g_kv[(size_t)s * 256 + 128 + lane * 4];
        __half2 k0, k1, v0, v1;
        memcpy(&k0, &kbits.x, 4); memcpy(&k1, &kbits.y, 4);
        memcpy(&v0, &vbits.x, 4); memcpy(&v1, &vbits.y, 4);
        float2 kf0 = __half22float2(k0), kf1 = __half22float2(k1);
        float p = q4.x * kf0.x + q4.y * kf0.y + q4.z * kf1.x + q4.w * kf1.y;
        p += __shfl_xor_sync(0xffffffffu, p, 1);
        p += __shfl_xor_sync(0xffffffffu, p, 2);
        p += __shfl_xor_sync(0xffffffffu, p, 4);
        float ev = __expf(p * scale);
        denom += ev;
        float2 vf0 = __half22float2(v0), vf1 = __half22float2(v1);
        acc.x += ev * vf0.x;
        acc.y += ev * vf0.y;
        acc.z += ev * vf1.x;
        acc.w += ev * vf1.y;
    }
    float inv = (r1 > r0) ? 1.f / denom : 0.f;
    __half2 o0 = __floats2half2_rn(acc.x * inv, acc.y * inv);
    __half2 o1 = __floats2half2_rn(acc.z * inv, acc.w * inv);
    uint2 ob;
    memcpy(&ob.x, &o0, 4); memcpy(&ob.y, &o1, 4);
    __stcs((uint2*)&g_agg[(size_t)w * CC + lane * 4], ob);
}

// -----------------------------------------------------------------------------
extern "C" void kernel_launch(void* const* d_in, const int* in_sizes, int n_in,
                              void* d_out, int out_size) {
    const float* x     = (const float*)d_in[0];
    const void*  ei    = d_in[1];
    const float* Wk    = (const float*)d_in[2];
    const float* bk    = (const float*)d_in[3];
    const float* Wq    = (const float*)d_in[4];
    const float* bq    = (const float*)d_in[5];
    const float* Wv    = (const float*)d_in[6];
    const float* bv    = (const float*)d_in[7];
    const float* a_rel = (const float*)d_in[8];
    const float* m_rel = (const float*)d_in[9];
    const float* p_rel = (const float*)d_in[10];
    const float* Wa    = (const float*)d_in[11];
    const float* ba    = (const float*)d_in[12];
    const float* skip  = (const float*)d_in[13];
    const float* Wfc   = (const float*)d_in[14];
    const float* bfc   = (const float*)d_in[15];
    float* out = (float*)d_out;

    int E = in_sizes[1] / 2;
    if (E > EE) E = EE;

    float *p_h, *p_b3;
    __half *p_qh, *p_kv, *p_w3h, *p_wah, *p_agg;
    cudaGetSymbolAddress((void**)&p_h, g_h);
    cudaGetSymbolAddress((void**)&p_agg, g_agg);
    cudaGetSymbolAddress((void**)&p_qh, g_qh);
    cudaGetSymbolAddress((void**)&p_kv, g_kv);
    cudaGetSymbolAddress((void**)&p_b3, g_b3);
    cudaGetSymbolAddress((void**)&p_w3h, g_w3h);
    cudaGetSymbolAddress((void**)&p_wah, g_wah);

    cudaFuncSetAttribute(k_qkv, cudaFuncAttributeMaxDynamicSharedMemorySize, SMEM_QKV);
    cudaFuncSetAttribute(k_out<false>, cudaFuncAttributeMaxDynamicSharedMemorySize, SMEM_OUT);
    cudaFuncSetAttribute(k_out<true>,  cudaFuncAttributeMaxDynamicSharedMemorySize, SMEM_OUT);

    int eb2 = (E / 2 + 255) / 256;
    int eb = (E + 255) / 256;
    int nb1024 = (NN + 1023) / 1024;
    int mtiles = (NN + 127) / 128;          // 782
    int sgrid = (NN * 32 + 255) / 256;      // 12500

    k_zero<<<(NN + 255) / 256, 256>>>(ei, NN);                 // 1
    k_convert<<<eb2, 256>>>(ei, E);                            // 2
    k_fold<<<(CC * 384 + 255) / 256, 256>>>(Wq, Wk, Wv, bq, bk, bv, a_rel, m_rel, 0); // 3
    k_qkv<<<mtiles, 256, SMEM_QKV>>>(x, p_w3h, p_b3, p_qh, p_kv, NN);                 // 4
    k_wh<<<(128 * 128 + 255) / 256, 256>>>(Wa, p_wah);                                // 5
    k_scan1<<<nb1024, 1024>>>(NN);                             // 6
    k_scan2<<<1, 128>>>(nb1024);                               // 7
    k_scan3<<<(NN + 255) / 256, 256>>>(NN, E);                 // 8
    k_scatter<<<eb, 256>>>(E);                                 // 9

    k_edge<<<sgrid, 256>>>(p_rel);                             // 10
    k_out<false><<<mtiles, 256, SMEM_OUT>>>(                   // 11
        p_agg, p_wah, ba, p_h, NN, x, skip, nullptr, nullptr, nullptr);

    k_fold<<<(CC * 384 + 255) / 256, 256>>>(Wq, Wk, Wv, bq, bk, bv, a_rel, m_rel, 1); // 12
    k_wh<<<(128 * 128 + 255) / 256, 256>>>(Wa + (size_t)CC * CC, p_wah);              // 13
    k_qkv<<<mtiles, 256, SMEM_QKV>>>(p_h, p_w3h, p_b3, p_qh, p_kv, NN);               // 14
    k_edge<<<sgrid, 256>>>(p_rel + HH);                        // 15
    k_out<true><<<mtiles, 256, SMEM_OUT>>>(                    // 16
        p_agg, p_wah, ba + CC, nullptr, NN, p_h, skip + 1, Wfc, bfc, out);
}

// round 15
// speedup vs baseline: 1.5417x; 1.0715x over previous
#include <cuda_runtime.h>
#include <cuda_bf16.h>
#include <cuda_fp16.h>
#include <math.h>
#include <stdint.h>

#define NN 100000
#define CC 128
#define EE 1600000
#define HH 4
#define DD 32
#define LL 2

// ---------------- device scratch (allocation-free: static globals) ----------
__device__ int   g_is64;
__device__ int   g_src[EE];
__device__ int   g_dst[EE];
__device__ int   g_srcs[EE];
__device__ int   g_count[NN];
__device__ int   g_rowstart[NN + 2];
__device__ int   g_cursor[NN];
__device__ int   g_bsum[128];
__device__ int   g_bsum2[128];
__device__ __half g_qh[(size_t)NN * 128];      // Q fp16
__device__ __half g_kv[(size_t)NN * 256];      // [n][0:128]=K' fp16  [128:256]=V' fp16
__device__ __half g_agg[(size_t)NN * CC];      // attention aggregate, fp16
__device__ __half g_h[(size_t)NN * CC];        // hidden state, fp16
__device__ float g_b3[384];
__device__ __half g_w3h[384 * 128];            // W3^T fp16: [n][c]
__device__ __half g_wah[128 * 128];            // Wa^T fp16: [n][c]

// ---------------- zero + edge-index dtype detection (fused) ------------------
__global__ void k_zero(const void* ei, int n) {
    int i = blockIdx.x * blockDim.x + threadIdx.x;
    if (i < n) g_count[i] = 0;
    if (blockIdx.x == 0 && threadIdx.x == 0) {
        const long long* q = (const long long*)ei;
        int is64 = 1;
        for (int k = 0; k < 64; k++) {
            long long v = q[k];
            if (v < 0 || v >= NN) { is64 = 0; break; }
        }
        g_is64 = is64;
    }
}

// 2 edges per thread, 16B vector loads
__global__ void k_convert(const void* ei, int E) {
    int t = blockIdx.x * blockDim.x + threadIdx.x;
    int e = t * 2;
    if (e >= E) return;
    bool two = (e + 1 < E);
    int s0, d0, s1 = 0, d1 = 0;
    if (g_is64) {
        const longlong2* ps = (const longlong2*)ei;
        const longlong2* pd = (const longlong2*)((const long long*)ei + E);
        longlong2 sv = ps[t], dv = pd[t];
        s0 = (int)sv.x; s1 = (int)sv.y;
        d0 = (int)dv.x; d1 = (int)dv.y;
    } else {
        const int2* ps = (const int2*)ei;
        const int2* pd = (const int2*)((const int*)ei + E);
        int2 sv = ps[t], dv = pd[t];
        s0 = sv.x; s1 = sv.y;
        d0 = dv.x; d1 = dv.y;
    }
    g_src[e] = s0; g_dst[e] = d0;
    atomicAdd(&g_count[d0], 1);
    if (two) {
        g_src[e + 1] = s1; g_dst[e + 1] = d1;
        atomicAdd(&g_count[d1], 1);
    }
}

// ---------------- counting sort by dst ---------------------------------------
__global__ void k_scan1(int n) {
    __shared__ int sh[1024];
    int i = blockIdx.x * 1024 + threadIdx.x;
    int v = (i < n) ? g_count[i] : 0;
    sh[threadIdx.x] = v;
    __syncthreads();
    for (int off = 1; off < 1024; off <<= 1) {
        int t = (threadIdx.x >= off) ? sh[threadIdx.x - off] : 0;
        __syncthreads();
        sh[threadIdx.x] += t;
        __syncthreads();
    }
    if (i < n) g_rowstart[i] = sh[threadIdx.x] - v;
    if (threadIdx.x == 1023) g_bsum[blockIdx.x] = sh[1023];
}

__global__ void k_scan2(int nb) {
    __shared__ int sh[128];
    int v = (threadIdx.x < nb) ? g_bsum[threadIdx.x] : 0;
    sh[threadIdx.x] = v;
    __syncthreads();
    for (int off = 1; off < 128; off <<= 1) {
        int t = (threadIdx.x >= off) ? sh[threadIdx.x - off] : 0;
        __syncthreads();
        sh[threadIdx.x] += t;
        __syncthreads();
    }
    g_bsum2[threadIdx.x] = sh[threadIdx.x] - v;
}

__global__ void k_scan3(int n, int E) {
    int i = blockIdx.x * blockDim.x + threadIdx.x;
    if (i < n) {
        int r = g_rowstart[i] + g_bsum2[i >> 10];
        g_rowstart[i] = r;
        g_cursor[i] = r;
    }
    if (i == 0) g_rowstart[n] = E;
}

__global__ void k_scatter(int E) {
    int e = blockIdx.x * blockDim.x + threadIdx.x;
    if (e >= E) return;
    int d = g_dst[e];
    int pos = atomicAdd(&g_cursor[d], 1);
    g_srcs[pos] = g_src[e];
}

// ---------------- fold relation transforms -> transposed fp16 W3 -------------
__global__ void k_fold(const float* __restrict__ Wq, const float* __restrict__ Wk,
                       const float* __restrict__ Wv, const float* __restrict__ bq,
                       const float* __restrict__ bk, const float* __restrict__ bv,
                       const float* __restrict__ a_rel, const float* __restrict__ m_rel,
                       int l) {
    int idx = blockIdx.x * blockDim.x + threadIdx.x;
    if (idx >= CC * 384) return;
    int c = idx / 384, j = idx % 384;
    float val;
    if (j < 128) {
        val = Wq[((size_t)l * CC + c) * CC + j];
    } else {
        int e = (j < 256) ? j - 128 : j - 256;
        int h = e >> 5, ee = e & 31;
        const float* Wx = (j < 256) ? Wk : Wv;
        const float* Rx = (j < 256) ? a_rel : m_rel;
        const float* wrow = Wx + ((size_t)l * CC + c) * CC + h * DD;
        const float* rr = Rx + ((size_t)(l * HH + h) * DD) * DD + ee;
        float s = 0.f;
#pragma unroll
        for (int d = 0; d < DD; d++) s += wrow[d] * rr[d * DD];
        val = s;
    }
    g_w3h[(size_t)j * 128 + c] = __float2half_rn(val);
    if (c == 0) {
        float bval;
        if (j < 128) {
            bval = bq[l * CC + j];
        } else {
            int e = (j < 256) ? j - 128 : j - 256;
            int h = e >> 5, ee = e & 31;
            const float* bx = (j < 256) ? bk : bv;
            const float* Rx = (j < 256) ? a_rel : m_rel;
            float s = 0.f;
#pragma unroll
            for (int d = 0; d < DD; d++)
                s += bx[l * CC + h * DD + d] * Rx[((size_t)(l * HH + h) * DD + d) * DD + ee];
            bval = s;
        }
        g_b3[j] = bval;
    }
}

// ---------------- transpose Wa -> fp16 ----------------------------------------
__global__ void k_wh(const float* __restrict__ W, __half* __restrict__ dst) {
    int idx = blockIdx.x * blockDim.x + threadIdx.x;
    if (idx >= 128 * 128) return;
    int n = idx >> 7, k = idx & 127;
    dst[(size_t)n * 128 + k] = __float2half_rn(W[(size_t)k * 128 + n]);
}

// ================= shared GEMM helpers ========================================
#define LDT 136

__device__ __forceinline__ void ldsm_x4(uint32_t& r0, uint32_t& r1, uint32_t& r2,
                                        uint32_t& r3, uint32_t addr) {
    asm volatile("ldmatrix.sync.aligned.m8n8.x4.shared.b16 {%0,%1,%2,%3}, [%4];"
                 : "=r"(r0), "=r"(r1), "=r"(r2), "=r"(r3) : "r"(addr));
}

__device__ __forceinline__ void mma16816_f16(float* d, const uint32_t* a,
                                             uint32_t b0, uint32_t b1) {
    asm volatile(
        "mma.sync.aligned.m16n8k16.row.col.f32.f16.f16.f32 "
        "{%0,%1,%2,%3}, {%4,%5,%6,%7}, {%8,%9}, {%0,%1,%2,%3};"
        : "+f"(d[0]), "+f"(d[1]), "+f"(d[2]), "+f"(d[3])
        : "r"(a[0]), "r"(a[1]), "r"(a[2]), "r"(a[3]), "r"(b0), "r"(b1));
}

#define CP_ASYNC16(dst_u32, src_ptr) \
    asm volatile("cp.async.cg.shared.global [%0], [%1], 16;" \
                 :: "r"(dst_u32), "l"(src_ptr))
#define CP_COMMIT() asm volatile("cp.async.commit_group;" ::: "memory")
#define CP_WAIT0()  asm volatile("cp.async.wait_group 0;" ::: "memory")

// ---------------- QKV GEMM: single-pass fp16, staged coalesced epilogue -------
// [Q|K'|V'] = A @ W3_fp16, fp16 outputs. CTA 128(M) x 128(N), NB=3.
// Warp tile 32x64 (4m x 2n). A16: A is fp16 (cp.async prologue); else fp32+cvt.
#define QK_A (128 * LDT * 2)
#define QK_B (128 * LDT * 2)
#define SMEM_QKV (QK_A + QK_B)

template <bool A16>
__global__ void __launch_bounds__(256, 2) k_qkv(
    const void* __restrict__ Ap,
    const __half* __restrict__ W,      // [384][128] fp16, n-major
    const float* __restrict__ bias,
    __half* __restrict__ qh,
    __half* __restrict__ kvout,
    int M) {
    extern __shared__ __align__(16) char smem[];
    uint32_t smem_base;
    asm("{ .reg .u64 t; cvta.to.shared.u64 t, %1; cvt.u32.u64 %0, t; }"
        : "=r"(smem_base) : "l"(smem));

    int tid = threadIdx.x, wid = tid >> 5, lane = tid & 31;
    int wm = wid & 3, wn = wid >> 2;
    int m0 = blockIdx.x * 128;

    // ---- A prologue
    if (A16) {
        const __half* A = (const __half*)Ap;
#pragma unroll
        for (int it = 0; it < 8; it++) {
            int idx = it * 256 + tid;
            int r = idx >> 4, u = idx & 15;
            int gr = m0 + r;
            if (gr >= M) gr = M - 1;
            const char* src = (const char*)&A[(size_t)gr * 128 + u * 8];
            uint32_t dst = smem_base + (uint32_t)(r * LDT + u * 8) * 2;
            CP_ASYNC16(dst, src);
        }
        CP_COMMIT();
    } else {
        const float* A = (const float*)Ap;
#pragma unroll
        for (int it = 0; it < 16; it++) {
            int idx = it * 256 + tid;
            int r = idx >> 5, u = idx & 31;
            int gr = m0 + r;
            if (gr >= M) gr = M - 1;
            float4 v = *(const float4*)&A[(size_t)gr * 128 + u * 4];
            __half2 h0 = __floats2half2_rn(v.x, v.y);
            __half2 h1 = __floats2half2_rn(v.z, v.w);
            uint32_t b0, b1;
            memcpy(&b0, &h0, 4); memcpy(&b1, &h1, 4);
            *(uint2*)(smem + (uint32_t)(r * LDT + u * 4) * 2) = make_uint2(b0, b1);
        }
    }

    uint32_t a_off[2], b_off[4];
#pragma unroll
    for (int mi = 0; mi < 2; mi++) {
        int arow = wm * 32 + mi * 16 + (lane & 7) + ((lane >> 3) & 1) * 8;
        int akc = (lane >> 4) * 8;
        a_off[mi] = (uint32_t)(arow * LDT + akc) * 2;
    }
#pragma unroll
    for (int p = 0; p < 4; p++) {
        int nrow = wn * 64 + p * 16 + (lane >> 4) * 8 + (lane & 7);
        int bkc = ((lane >> 3) & 1) * 8;
        b_off[p] = (uint32_t)(nrow * LDT + bkc) * 2;
    }
    int groupID = lane >> 2, tg = lane & 3;
    __half* stage = (__half*)(smem + QK_A);   // reuse B region for epilogue

    for (int bt = 0; bt < 3; bt++) {
        int n0 = bt * 128;
        __syncthreads();
        {
            const char* Wb = (const char*)W;
#pragma unroll
            for (int it = 0; it < 8; it++) {
                int idx = it * 256 + tid;
                int r = idx >> 4, u = idx & 15;
                const char* src = Wb + (size_t)(n0 + r) * 256 + u * 16;
                uint32_t dst = smem_base + QK_A + (uint32_t)(r * LDT + u * 8) * 2;
                CP_ASYNC16(dst, src);
            }
            CP_COMMIT();
            CP_WAIT0();
        }
        __syncthreads();

        float acc[2][8][4];
#pragma unroll
        for (int mi = 0; mi < 2; mi++)
#pragma unroll
            for (int ni = 0; ni < 8; ni++)
#pragma unroll
                for (int c = 0; c < 4; c++) acc[mi][ni][c] = 0.f;

#pragma unroll
        for (int ks = 0; ks < 8; ks++) {
            uint32_t kb = (uint32_t)ks * 32;
            uint32_t a[2][4], b[8][2];
#pragma unroll
            for (int mi = 0; mi < 2; mi++)
                ldsm_x4(a[mi][0], a[mi][1], a[mi][2], a[mi][3],
                        smem_base + a_off[mi] + kb);
#pragma unroll
            for (int p = 0; p < 4; p++) {
                uint32_t r0, r1, r2, r3;
                ldsm_x4(r0, r1, r2, r3, smem_base + QK_A + b_off[p] + kb);
                b[p * 2][0] = r0; b[p * 2][1] = r1;
                b[p * 2 + 1][0] = r2; b[p * 2 + 1][1] = r3;
            }
#pragma unroll
            for (int mi = 0; mi < 2; mi++)
#pragma unroll
                for (int ni = 0; ni < 8; ni++)
                    mma16816_f16(acc[mi][ni], a[mi], b[ni][0], b[ni][1]);
        }

        // ---- staged epilogue: acc -> smem (conflict-free) -> coalesced stores
        __syncthreads();   // all ldsm B reads done before overwrite
#pragma unroll
        for (int mi = 0; mi < 2; mi++) {
#pragma unroll
            for (int hh = 0; hh < 2; hh++) {
                int rowl = wm * 32 + mi * 16 + groupID + hh * 8;
#pragma unroll
                for (int ni = 0; ni < 8; ni++) {
                    int col = wn * 64 + ni * 8 + tg * 2;
                    float v0 = acc[mi][ni][hh * 2]     + bias[n0 + col];
                    float v1 = acc[mi][ni][hh * 2 + 1] + bias[n0 + col + 1];
                    __half2 hv = __floats2half2_rn(v0, v1);
                    *(__half2*)&stage[rowl * LDT + col] = hv;
                }
            }
        }
        __syncthreads();
#pragma unroll
        for (int it = 0; it < 8; it++) {
            int idx = it * 256 + tid;
            int r = idx >> 4, u = idx & 15;
            int gr = m0 + r;
            if (gr < M) {
                uint4 val = *(const uint4*)&stage[r * LDT + u * 8];
                if (bt == 0)
                    *(uint4*)&qh[(size_t)gr * 128 + u * 8] = val;
                else
                    *(uint4*)&kvout[(size_t)gr * 256 + (bt - 1) * 128 + u * 8] = val;
            }
        }
    }
}

// ---------------- output GEMM: fp16 + GELU + blend; h fp16 out (+FC) ----------
#define SM_OFC (QK_A + QK_B)
#define SMEM_OUT (SM_OFC + 2048)

template <bool FC, bool HF16>
__global__ void __launch_bounds__(256, 2) k_out(
    const __half* __restrict__ Aagg,   // [M][128] fp16
    const __half* __restrict__ W,      // [128][128] fp16, n-major
    const float* __restrict__ bias,
    __half* __restrict__ Ch,           // h fp16 out (when !FC)
    int M,
    const void* __restrict__ holdp,    // fp32 (l0) or fp16 (l1)
    const float* __restrict__ skipp,
    const float* __restrict__ Wfc,
    const float* __restrict__ bfc,
    float* __restrict__ outp) {
    extern __shared__ __align__(16) char smem[];
    uint32_t smem_base;
    asm("{ .reg .u64 t; cvta.to.shared.u64 t, %1; cvt.u32.u64 %0, t; }"
        : "=r"(smem_base) : "l"(smem));

    int tid = threadIdx.x, wid = tid >> 5, lane = tid & 31;
    int wm = wid & 3, wn = wid >> 2;
    int m0 = blockIdx.x * 128;

    // ---- B tile via cp.async; agg fp16 -> GELU -> fp16 smem
    {
        const char* Wb = (const char*)W;
#pragma unroll
        for (int it = 0; it < 8; it++) {
            int idx = it * 256 + tid;
            int r = idx >> 4, u = idx & 15;
            const char* src = Wb + (size_t)r * 256 + u * 16;
            uint32_t dst = smem_base + QK_A + (uint32_t)(r * LDT + u * 8) * 2;
            CP_ASYNC16(dst, src);
        }
        CP_COMMIT();
    }
#pragma unroll
    for (int it = 0; it < 8; it++) {
        int idx = it * 256 + tid;
        int r = idx >> 4, u = idx & 15;
        int gr = m0 + r;
        if (gr >= M) gr = M - 1;
        uint4 bits = *(const uint4*)&Aagg[(size_t)gr * 128 + u * 8];
        __half2 p0, p1, p2, p3;
        memcpy(&p0, &bits.x, 4); memcpy(&p1, &bits.y, 4);
        memcpy(&p2, &bits.z, 4); memcpy(&p3, &bits.w, 4);
        float2 f0 = __half22float2(p0), f1 = __half22float2(p1);
        float2 f2 = __half22float2(p2), f3 = __half22float2(p3);
        f0.x *= normcdff(f0.x); f0.y *= normcdff(f0.y);
        f1.x *= normcdff(f1.x); f1.y *= normcdff(f1.y);
        f2.x *= normcdff(f2.x); f2.y *= normcdff(f2.y);
        f3.x *= normcdff(f3.x); f3.y *= normcdff(f3.y);
        __half2 o0 = __floats2half2_rn(f0.x, f0.y);
        __half2 o1 = __floats2half2_rn(f1.x, f1.y);
        __half2 o2 = __floats2half2_rn(f2.x, f2.y);
        __half2 o3 = __floats2half2_rn(f3.x, f3.y);
        uint4 ob;
        memcpy(&ob.x, &o0, 4); memcpy(&ob.y, &o1, 4);
        memcpy(&ob.z, &o2, 4); memcpy(&ob.w, &o3, 4);
        *(uint4*)(smem + (uint32_t)(r * LDT + u * 8) * 2) = ob;
    }
    CP_WAIT0();
    __syncthreads();

    uint32_t a_off[2], b_off[4];
#pragma unroll
    for (int mi = 0; mi < 2; mi++) {
        int arow = wm * 32 + mi * 16 + (lane & 7) + ((lane >> 3) & 1) * 8;
        int akc = (lane >> 4) * 8;
        a_off[mi] = (uint32_t)(arow * LDT + akc) * 2;
    }
#pragma unroll
    for (int p = 0; p < 4; p++) {
        int nrow = wn * 64 + p * 16 + (lane >> 4) * 8 + (lane & 7);
        int bkc = ((lane >> 3) & 1) * 8;
        b_off[p] = (uint32_t)(nrow * LDT + bkc) * 2;
    }
    int groupID = lane >> 2, tg = lane & 3;
    float g = 1.f / (1.f + __expf(-skipp[0]));
    float og = 1.f - g;

    float acc[2][8][4];
#pragma unroll
    for (int mi = 0; mi < 2; mi++)
#pragma unroll
        for (int ni = 0; ni < 8; ni++)
#pragma unroll
            for (int c = 0; c < 4; c++) acc[mi][ni][c] = 0.f;

#pragma unroll
    for (int ks = 0; ks < 8; ks++) {
        uint32_t kb = (uint32_t)ks * 32;
        uint32_t a[2][4], b[8][2];
#pragma unroll
        for (int mi = 0; mi < 2; mi++)
            ldsm_x4(a[mi][0], a[mi][1], a[mi][2], a[mi][3],
                    smem_base + a_off[mi] + kb);
#pragma unroll
        for (int p = 0; p < 4; p++) {
            uint32_t r0, r1, r2, r3;
            ldsm_x4(r0, r1, r2, r3, smem_base + QK_A + b_off[p] + kb);
            b[p * 2][0] = r0; b[p * 2][1] = r1;
            b[p * 2 + 1][0] = r2; b[p * 2 + 1][1] = r3;
        }
#pragma unroll
        for (int mi = 0; mi < 2; mi++)
#pragma unroll
            for (int ni = 0; ni < 8; ni++)
                mma16816_f16(acc[mi][ni], a[mi], b[ni][0], b[ni][1]);
    }

    float fc0[2][2], fc1[2][2];
    if (FC) {
#pragma unroll
        for (int mi = 0; mi < 2; mi++)
#pragma unroll
            for (int hh = 0; hh < 2; hh++) { fc0[mi][hh] = 0.f; fc1[mi][hh] = 0.f; }
    }
    __half* stage = (__half*)(smem + QK_A);
    if (!FC) __syncthreads();   // B reads done before staging overwrite

#pragma unroll
    for (int mi = 0; mi < 2; mi++) {
#pragma unroll
        for (int hh = 0; hh < 2; hh++) {
            int rowl = wm * 32 + mi * 16 + groupID + hh * 8;
            int row = m0 + rowl;
#pragma unroll
            for (int ni = 0; ni < 8; ni++) {
                int col = wn * 64 + ni * 8 + tg * 2;
                float v0 = acc[mi][ni][hh * 2]     + bias[col];
                float v1 = acc[mi][ni][hh * 2 + 1] + bias[col + 1];
                float hx, hy;
                if (HF16) {
                    uint32_t hb = *(const uint32_t*)&((const __half*)holdp)[(size_t)row * 128 + col];
                    __half2 hh2; memcpy(&hh2, &hb, 4);
                    float2 hf = __half22float2(hh2);
                    hx = hf.x; hy = hf.y;
                } else {
                    float2 hf = *(const float2*)&((const float*)holdp)[(size_t)row * 128 + col];
                    hx = hf.x; hy = hf.y;
                }
                v0 = g * v0 + og * hx;
                v1 = g * v1 + og * hy;
                if (!FC) {
                    *(__half2*)&stage[rowl * LDT + col] = __floats2half2_rn(v0, v1);
                } else {
                    fc0[mi][hh] += v0 * Wfc[col * 2]     + v1 * Wfc[col * 2 + 2];
                    fc1[mi][hh] += v0 * Wfc[col * 2 + 1] + v1 * Wfc[col * 2 + 3];
                }
            }
        }
    }

    if (!FC) {
        __syncthreads();
#pragma unroll
        for (int it = 0; it < 8; it++) {
            int idx = it * 256 + tid;
            int r = idx >> 4, u = idx & 15;
            int gr = m0 + r;
            if (gr < M) {
                uint4 val = *(const uint4*)&stage[r * LDT + u * 8];
                *(uint4*)&Ch[(size_t)gr * 128 + u * 8] = val;
            }
        }
    } else {
        float* fcbuf = (float*)(smem + SM_OFC);
#pragma unroll
        for (int mi = 0; mi < 2; mi++) {
#pragma unroll
            for (int hh = 0; hh < 2; hh++) {
                float a0 = fc0[mi][hh], a1 = fc1[mi][hh];
                a0 += __shfl_xor_sync(0xffffffffu, a0, 1);
                a0 += __shfl_xor_sync(0xffffffffu, a0, 2);
                a1 += __shfl_xor_sync(0xffffffffu, a1, 1);
                a1 += __shfl_xor_sync(0xffffffffu, a1, 2);
                int rowl = wm * 32 + mi * 16 + groupID + hh * 8;
                if (tg == 0) {
                    fcbuf[(wn * 128 + rowl) * 2]     = a0;
                    fcbuf[(wn * 128 + rowl) * 2 + 1] = a1;
                }
            }
        }
        __syncthreads();
        if (tid < 128) {
            int gr = m0 + tid;
            if (gr < M) {
                float o0 = fcbuf[tid * 2]     + fcbuf[(128 + tid) * 2]     + bfc[0];
                float o1 = fcbuf[tid * 2 + 1] + fcbuf[(128 + tid) * 2 + 1] + bfc[1];
                outp[(size_t)gr * 2]     = o0;
                outp[(size_t)gr * 2 + 1] = o1;
            }
        }
    }
}

// ---------------- edge phase: one warp per dst node, 4-edge batched -----------
__global__ void __launch_bounds__(256) k_edge(const float* __restrict__ prel) {
    int w = (blockIdx.x * blockDim.x + threadIdx.x) >> 5;
    int lane = threadIdx.x & 31;
    if (w >= NN) return;
    int r0 = g_rowstart[w], r1 = g_rowstart[w + 1];
    int h = lane >> 3;
    uint2 qb = __ldcs((const uint2*)&g_qh[(size_t)w * 128 + lane * 4]);
    __half2 qh0, qh1;
    memcpy(&qh0, &qb.x, 4); memcpy(&qh1, &qb.y, 4);
    float2 qf0 = __half22float2(qh0), qf1 = __half22float2(qh1);
    const float4 q4 = {qf0.x, qf0.y, qf1.x, qf1.y};
    const float scale = prel[h] * 0.17677669529663687f;
    float denom = 0.f;
    float4 acc = {0.f, 0.f, 0.f, 0.f};

    int j = r0;
    for (; j + 4 <= r1; j += 4) {
        int s[4];
#pragma unroll
        for (int u = 0; u < 4; u++) s[u] = __ldcs(&g_srcs[j + u]);
        uint2 kb[4], vb[4];
#pragma unroll
        for (int u = 0; u < 4; u++) {
            kb[u] = *(const uint2*)&g_kv[(size_t)s[u] * 256 + lane * 4];
            vb[u] = *(const uint2*)&g_kv[(size_t)s[u] * 256 + 128 + lane * 4];
        }
        float ev[4];
#pragma unroll
        for (int u = 0; u < 4; u++) {
            __half2 k0, k1;
            memcpy(&k0, &kb[u].x, 4); memcpy(&k1, &kb[u].y, 4);
            float2 kf0 = __half22float2(k0), kf1 = __half22float2(k1);
            float p = q4.x * kf0.x + q4.y * kf0.y + q4.z * kf1.x + q4.w * kf1.y;
            p += __shfl_xor_sync(0xffffffffu, p, 1);
            p += __shfl_xor_sync(0xffffffffu, p, 2);
            p += __shfl_xor_sync(0xffffffffu, p, 4);
            ev[u] = __expf(p * scale);
        }
#pragma unroll
        for (int u = 0; u < 4; u++) {
            __half2 v0, v1;
            memcpy(&v0, &vb[u].x, 4); memcpy(&v1, &vb[u].y, 4);
            float2 vf0 = __half22float2(v0), vf1 = __half22float2(v1);
            denom += ev[u];
            acc.x += ev[u] * vf0.x;
            acc.y += ev[u] * vf0.y;
            acc.z += ev[u] * vf1.x;
            acc.w += ev[u] * vf1.y;
        }
    }
    for (; j < r1; j++) {
        int s = __ldcs(&g_srcs[j]);
        uint2 kbits = *(const uint2*)&g_kv[(size_t)s * 256 + lane * 4];
        uint2 vbits = *(const uint2*)&g_kv[(size_t)s * 256 + 128 + lane * 4];
        __half2 k0, k1, v0, v1;
        memcpy(&k0, &kbits.x, 4); memcpy(&k1, &kbits.y, 4);
        memcpy(&v0, &vbits.x, 4); memcpy(&v1, &vbits.y, 4);
        float2 kf0 = __half22float2(k0), kf1 = __half22float2(k1);
        float p = q4.x * kf0.x + q4.y * kf0.y + q4.z * kf1.x + q4.w * kf1.y;
        p += __shfl_xor_sync(0xffffffffu, p, 1);
        p += __shfl_xor_sync(0xffffffffu, p, 2);
        p += __shfl_xor_sync(0xffffffffu, p, 4);
        float ev = __expf(p * scale);
        denom += ev;
        float2 vf0 = __half22float2(v0), vf1 = __half22float2(v1);
        acc.x += ev * vf0.x;
        acc.y += ev * vf0.y;
        acc.z += ev * vf1.x;
        acc.w += ev * vf1.y;
    }
    float inv = (r1 > r0) ? 1.f / denom : 0.f;
    __half2 o0 = __floats2half2_rn(acc.x * inv, acc.y * inv);
    __half2 o1 = __floats2half2_rn(acc.z * inv, acc.w * inv);
    uint2 ob;
    memcpy(&ob.x, &o0, 4); memcpy(&ob.y, &o1, 4);
    __stcs((uint2*)&g_agg[(size_t)w * CC + lane * 4], ob);
}

// -----------------------------------------------------------------------------
extern "C" void kernel_launch(void* const* d_in, const int* in_sizes, int n_in,
                              void* d_out, int out_size) {
    const float* x     = (const float*)d_in[0];
    const void*  ei    = d_in[1];
    const float* Wk    = (const float*)d_in[2];
    const float* bk    = (const float*)d_in[3];
    const float* Wq    = (const float*)d_in[4];
    const float* bq    = (const float*)d_in[5];
    const float* Wv    = (const float*)d_in[6];
    const float* bv    = (const float*)d_in[7];
    const float* a_rel = (const float*)d_in[8];
    const float* m_rel = (const float*)d_in[9];
    const float* p_rel = (const float*)d_in[10];
    const float* Wa    = (const float*)d_in[11];
    const float* ba    = (const float*)d_in[12];
    const float* skip  = (const float*)d_in[13];
    const float* Wfc   = (const float*)d_in[14];
    const float* bfc   = (const float*)d_in[15];
    float* out = (float*)d_out;

    int E = in_sizes[1] / 2;
    if (E > EE) E = EE;

    float *p_b3;
    __half *p_qh, *p_kv, *p_w3h, *p_wah, *p_agg, *p_h;
    cudaGetSymbolAddress((void**)&p_h, g_h);
    cudaGetSymbolAddress((void**)&p_agg, g_agg);
    cudaGetSymbolAddress((void**)&p_qh, g_qh);
    cudaGetSymbolAddress((void**)&p_kv, g_kv);
    cudaGetSymbolAddress((void**)&p_b3, g_b3);
    cudaGetSymbolAddress((void**)&p_w3h, g_w3h);
    cudaGetSymbolAddress((void**)&p_wah, g_wah);

    cudaFuncSetAttribute(k_qkv<false>, cudaFuncAttributeMaxDynamicSharedMemorySize, SMEM_QKV);
    cudaFuncSetAttribute(k_qkv<true>,  cudaFuncAttributeMaxDynamicSharedMemorySize, SMEM_QKV);
    cudaFuncSetAttribute((const void*)k_out<false, false>, cudaFuncAttributeMaxDynamicSharedMemorySize, SMEM_OUT);
    cudaFuncSetAttribute((const void*)k_out<true, true>,   cudaFuncAttributeMaxDynamicSharedMemorySize, SMEM_OUT);

    int eb2 = (E / 2 + 255) / 256;
    int eb = (E + 255) / 256;
    int nb1024 = (NN + 1023) / 1024;
    int mtiles = (NN + 127) / 128;          // 782
    int sgrid = (NN * 32 + 255) / 256;      // 12500

    k_zero<<<(NN + 255) / 256, 256>>>(ei, NN);                 // 1
    k_convert<<<eb2, 256>>>(ei, E);                            // 2
    k_fold<<<(CC * 384 + 255) / 256, 256>>>(Wq, Wk, Wv, bq, bk, bv, a_rel, m_rel, 0); // 3
    k_qkv<false><<<mtiles, 256, SMEM_QKV>>>(x, p_w3h, p_b3, p_qh, p_kv, NN);          // 4
    k_wh<<<(128 * 128 + 255) / 256, 256>>>(Wa, p_wah);                                // 5
    k_scan1<<<nb1024, 1024>>>(NN);                             // 6
    k_scan2<<<1, 128>>>(nb1024);                               // 7
    k_scan3<<<(NN + 255) / 256, 256>>>(NN, E);                 // 8
    k_scatter<<<eb, 256>>>(E);                                 // 9

    k_edge<<<sgrid, 256>>>(p_rel);                             // 10
    k_out<false, false><<<mtiles, 256, SMEM_OUT>>>(            // 11
        p_agg, p_wah, ba, p_h, NN, x, skip, nullptr, nullptr, nullptr);

    k_fold<<<(CC * 384 + 255) / 256, 256>>>(Wq, Wk, Wv, bq, bk, bv, a_rel, m_rel, 1); // 12
    k_wh<<<(128 * 128 + 255) / 256, 256>>>(Wa + (size_t)CC * CC, p_wah);              // 13
    k_qkv<true><<<mtiles, 256, SMEM_QKV>>>(p_h, p_w3h, p_b3, p_qh, p_kv, NN);         // 14
    k_edge<<<sgrid, 256>>>(p_rel + HH);                        // 15
    k_out<true, true><<<mtiles, 256, SMEM_OUT>>>(              // 16
        p_agg, p_wah, ba + CC, nullptr, NN, p_h, skip + 1, Wfc, bfc, out);
}